// round 12
// baseline (speedup 1.0000x reference)
#include <cuda_runtime.h>
#include <cuda_bf16.h>
#include <math.h>
#include <stdint.h>

#define SEQ 2048
#define EMB 1024
#define NH  16
#define HD  64

// Scratch (device globals — no allocation allowed)
__device__ __nv_bfloat16 g_Q[NH * SEQ * HD];
__device__ __nv_bfloat16 g_K[NH * SEQ * HD];
__device__ __nv_bfloat16 g_V[NH * SEQ * HD];
__device__ __nv_bfloat16 g_S[(size_t)NH * SEQ * SEQ];   // scores, then exp values
__device__ unsigned short g_LUT[65536];                 // bf16(expf(bf16)) table
__device__ float g_attn[SEQ * EMB];

__device__ __forceinline__ float bf16r(float v) {
    return __bfloat162float(__float2bfloat16(v));
}
__device__ __forceinline__ uint32_t f2tf32(float x) {
    uint32_t r;
    asm("cvt.rna.tf32.f32 %0, %1;" : "=r"(r) : "f"(x));
    return r;
}

// ---------------- mma.sync helpers ----------------
__device__ __forceinline__ uint32_t smem_u32(const void* p) {
    return (uint32_t)__cvta_generic_to_shared(p);
}
__device__ __forceinline__ void ldsm_x4(uint32_t& a0, uint32_t& a1,
                                        uint32_t& a2, uint32_t& a3, uint32_t addr) {
    asm volatile("ldmatrix.sync.aligned.m8n8.x4.shared.b16 {%0,%1,%2,%3}, [%4];\n"
                 : "=r"(a0), "=r"(a1), "=r"(a2), "=r"(a3) : "r"(addr));
}
__device__ __forceinline__ void ldsm_x2(uint32_t& b0, uint32_t& b1, uint32_t addr) {
    asm volatile("ldmatrix.sync.aligned.m8n8.x2.shared.b16 {%0,%1}, [%2];\n"
                 : "=r"(b0), "=r"(b1) : "r"(addr));
}
__device__ __forceinline__ void ldsm_x2_t(uint32_t& b0, uint32_t& b1, uint32_t addr) {
    asm volatile("ldmatrix.sync.aligned.m8n8.x2.trans.shared.b16 {%0,%1}, [%2];\n"
                 : "=r"(b0), "=r"(b1) : "r"(addr));
}
__device__ __forceinline__ void mma16816(float& d0, float& d1, float& d2, float& d3,
                                         uint32_t a0, uint32_t a1, uint32_t a2, uint32_t a3,
                                         uint32_t b0, uint32_t b1) {
    asm volatile("mma.sync.aligned.m16n8k16.row.col.f32.bf16.bf16.f32 "
                 "{%0,%1,%2,%3},{%4,%5,%6,%7},{%8,%9},{%0,%1,%2,%3};\n"
                 : "+f"(d0), "+f"(d1), "+f"(d2), "+f"(d3)
                 : "r"(a0), "r"(a1), "r"(a2), "r"(a3), "r"(b0), "r"(b1));
}
__device__ __forceinline__ void mma_tf32(float* d, const uint32_t* a,
                                         const uint32_t* b) {
    asm volatile("mma.sync.aligned.m16n8k8.row.col.f32.tf32.tf32.f32 "
                 "{%0,%1,%2,%3},{%4,%5,%6,%7},{%8,%9},{%0,%1,%2,%3};\n"
                 : "+f"(d[0]), "+f"(d[1]), "+f"(d[2]), "+f"(d[3])
                 : "r"(a[0]), "r"(a[1]), "r"(a[2]), "r"(a[3]), "r"(b[0]), "r"(b[1]));
}

// ---------------- cp.async helpers ----------------
__device__ __forceinline__ void cp_async16(uint32_t smem_addr, const void* gptr) {
    asm volatile("cp.async.cg.shared.global [%0], [%1], 16;\n"
                 :: "r"(smem_addr), "l"(gptr));
}
__device__ __forceinline__ void cp_commit() {
    asm volatile("cp.async.commit_group;\n" ::: "memory");
}
__device__ __forceinline__ void cp_wait0() {
    asm volatile("cp.async.wait_group 0;\n" ::: "memory");
}
__device__ __forceinline__ void bar_sync(int id) {
    asm volatile("bar.sync %0, 128;\n" :: "r"(id) : "memory");
}

// ---------------------------------------------------------------------------
// LUT fill: LUT[i] = bits(bf16(expf(float(bf16_from_bits(i))))).
// Uses the SAME expf as the previous bit-exact kernels -> lookups bitwise
// identical to computing inline.
// ---------------------------------------------------------------------------
__global__ __launch_bounds__(256) void fill_lut()
{
    int i = blockIdx.x * 256 + threadIdx.x;
    __nv_bfloat16 t = __ushort_as_bfloat16((unsigned short)i);
    float e = bf16r(expf(__bfloat162float(t)));
    g_LUT[i] = __bfloat16_as_ushort(__float2bfloat16(e));
}

// ---------------------------------------------------------------------------
// Fused QKV projection — sequential-K FFMA (bit-exact vs reference), Kc=16,
// double-buffered smem, register prefetch. Per-output FMA order unchanged.
// ---------------------------------------------------------------------------
__global__ __launch_bounds__(256) void proj_qkv_kernel(
    const float* __restrict__ x,
    const float* __restrict__ Wq, const float* __restrict__ bq,
    const float* __restrict__ Wk, const float* __restrict__ bk,
    const float* __restrict__ Wv, const float* __restrict__ bv)
{
    const float* W; const float* bias; __nv_bfloat16* out;
    if (blockIdx.z == 0)      { W = Wq; bias = bq; out = g_Q; }
    else if (blockIdx.z == 1) { W = Wk; bias = bk; out = g_K; }
    else                      { W = Wv; bias = bv; out = g_V; }

    __shared__ float As[2][16][128];
    __shared__ float Bs[2][16][128];
    const int tid = threadIdx.x;
    const int tx = tid & 15, ty = tid >> 4;
    const int bM = blockIdx.y * 128, bN = blockIdx.x * 128;

    float acc[8][8] = {};

    // staging coords: A 128x16 (2 float4/thread), B 16x128 (2 float4/thread)
    const int a_row0 = tid >> 2,        a_c0 = (tid & 3) * 4;
    const int a_row1 = (tid + 256) >> 2, a_c1 = ((tid + 256) & 3) * 4;
    const int b_kr0 = tid >> 5,         b_c0 = (tid & 31) * 4;
    const int b_kr1 = (tid + 256) >> 5, b_c1 = ((tid + 256) & 31) * 4;

    float4 pa0 = *(const float4*)(x + (size_t)(bM + a_row0) * EMB + a_c0);
    float4 pa1 = *(const float4*)(x + (size_t)(bM + a_row1) * EMB + a_c1);
    float4 pb0 = *(const float4*)(W + (size_t)b_kr0 * EMB + bN + b_c0);
    float4 pb1 = *(const float4*)(W + (size_t)b_kr1 * EMB + bN + b_c1);

    for (int k0 = 0; k0 < EMB; k0 += 16) {
        const int b = (k0 >> 4) & 1;
        As[b][a_c0 + 0][a_row0] = pa0.x; As[b][a_c0 + 1][a_row0] = pa0.y;
        As[b][a_c0 + 2][a_row0] = pa0.z; As[b][a_c0 + 3][a_row0] = pa0.w;
        As[b][a_c1 + 0][a_row1] = pa1.x; As[b][a_c1 + 1][a_row1] = pa1.y;
        As[b][a_c1 + 2][a_row1] = pa1.z; As[b][a_c1 + 3][a_row1] = pa1.w;
        *(float4*)&Bs[b][b_kr0][b_c0] = pb0;
        *(float4*)&Bs[b][b_kr1][b_c1] = pb1;
        __syncthreads();

        if (k0 + 16 < EMB) {
            pa0 = *(const float4*)(x + (size_t)(bM + a_row0) * EMB + k0 + 16 + a_c0);
            pa1 = *(const float4*)(x + (size_t)(bM + a_row1) * EMB + k0 + 16 + a_c1);
            pb0 = *(const float4*)(W + (size_t)(k0 + 16 + b_kr0) * EMB + bN + b_c0);
            pb1 = *(const float4*)(W + (size_t)(k0 + 16 + b_kr1) * EMB + bN + b_c1);
        }

        #pragma unroll
        for (int kk = 0; kk < 16; kk++) {
            float a[8], bb[8];
            *(float4*)&a[0]  = *(float4*)&As[b][kk][ty * 8];
            *(float4*)&a[4]  = *(float4*)&As[b][kk][ty * 8 + 4];
            *(float4*)&bb[0] = *(float4*)&Bs[b][kk][tx * 8];
            *(float4*)&bb[4] = *(float4*)&Bs[b][kk][tx * 8 + 4];
            #pragma unroll
            for (int i = 0; i < 8; i++)
                #pragma unroll
                for (int j = 0; j < 8; j++)
                    acc[i][j] = fmaf(a[i], bb[j], acc[i][j]);
        }
    }

    #pragma unroll
    for (int i = 0; i < 8; i++) {
        int m = bM + ty * 8 + i;
        #pragma unroll
        for (int j = 0; j < 8; j++) {
            int n = bN + tx * 8 + j;
            float v = acc[i][j] + bias[n];
            out[(size_t)(n >> 6) * SEQ * HD + (size_t)m * HD + (n & 63)] =
                __float2bfloat16(v);
        }
    }
}

// ---------------------------------------------------------------------------
// Causal attention. Phase 1/3 as round 11 (bit-safe). Phase 2 uses the exp
// LUT (bitwise identical). Phase 3 divide replaced by per-row reciprocal
// multiply (only numerics change; ~1e-6 drift).
// ---------------------------------------------------------------------------
__device__ __forceinline__ void stage_tile(uint32_t dst, const __nv_bfloat16* src,
                                           int wtid) {
    #pragma unroll
    for (int u = 0; u < 4; u++) {
        int idx = wtid + u * 128;
        int r = idx >> 3, s = idx & 7;
        cp_async16(dst + (uint32_t)((r * 72 + s * 8) * 2), src + r * 64 + s * 8);
    }
}

__device__ void attn_qtile(
    int qt, int h, __nv_bfloat16* Qs, __nv_bfloat16* KV2,
    float* mrow, float* Lrow, float* psum, int wtid, int barid)
{
    const int lane = wtid & 31;
    const int warp = wtid >> 5;
    const int r0   = warp * 16;
    const int len  = (qt + 1) * 64;

    const size_t qbase = ((size_t)h * SEQ + (size_t)qt * 64) * HD;
    const size_t srow0 = ((size_t)h * SEQ + (size_t)qt * 64) * SEQ;
    const __nv_bfloat16* Kh = g_K + (size_t)h * SEQ * HD;
    const __nv_bfloat16* Vh = g_V + (size_t)h * SEQ * HD;

    const uint32_t kvb0 = smem_u32(KV2);
    const uint32_t kvb1 = kvb0 + 64 * 72 * 2;

    for (int idx = wtid; idx < 64 * 8; idx += 128) {
        int r = idx >> 3, s = idx & 7;
        *(uint4*)&Qs[r * 72 + s * 8] = *(const uint4*)&g_Q[qbase + r * 64 + s * 8];
    }
    bar_sync(barid);

    uint32_t aq[4][4];
    {
        const uint32_t qb = smem_u32(Qs);
        #pragma unroll
        for (int ks = 0; ks < 4; ks++) {
            uint32_t addr = qb +
                (uint32_t)((r0 + (lane & 7) + ((lane >> 3) & 1) * 8) * 144 +
                           ((lane >> 4) * 16) + ks * 32);
            ldsm_x4(aq[ks][0], aq[ks][1], aq[ks][2], aq[ks][3], addr);
        }
    }

    // ================= PHASE 1: S -> g_S, running row max =================
    float rm0 = -INFINITY, rm1 = -INFINITY;
    const int rA = r0 + (lane >> 2);

    stage_tile(kvb0, Kh, wtid);
    cp_commit();

    for (int kt = 0; kt <= qt; kt++) {
        cp_wait0();
        bar_sync(barid);
        const uint32_t kvb = (kt & 1) ? kvb1 : kvb0;
        if (kt < qt) {
            stage_tile((kt & 1) ? kvb0 : kvb1, Kh + (size_t)(kt + 1) * 64 * HD, wtid);
            cp_commit();
        }

        const bool diag = (kt == qt);
        #pragma unroll
        for (int nt = 0; nt < 8; nt++) {
            float c0 = 0.f, c1 = 0.f, c2 = 0.f, c3 = 0.f;
            #pragma unroll
            for (int ks = 0; ks < 4; ks++) {
                int l2 = lane & 15;
                uint32_t addr = kvb +
                    (uint32_t)((nt * 8 + (l2 & 7)) * 144 + (l2 >> 3) * 16 + ks * 32);
                uint32_t b0, b1;
                ldsm_x2(b0, b1, addr);
                mma16816(c0, c1, c2, c3,
                         aq[ks][0], aq[ks][1], aq[ks][2], aq[ks][3], b0, b1);
            }
            const int cc = nt * 8 + (lane & 3) * 2;
            float s00 = bf16r(c0) * 0.5f;
            float s01 = bf16r(c1) * 0.5f;
            float s10 = bf16r(c2) * 0.5f;
            float s11 = bf16r(c3) * 0.5f;
            if (diag) {
                if (cc     > rA)     s00 = -INFINITY;
                if (cc + 1 > rA)     s01 = -INFINITY;
                if (cc     > rA + 8) s10 = -INFINITY;
                if (cc + 1 > rA + 8) s11 = -INFINITY;
            }
            rm0 = fmaxf(rm0, fmaxf(s00, s01));
            rm1 = fmaxf(rm1, fmaxf(s10, s11));
            __nv_bfloat162 p0; p0.x = __float2bfloat16(s00); p0.y = __float2bfloat16(s01);
            __nv_bfloat162 p1; p1.x = __float2bfloat16(s10); p1.y = __float2bfloat16(s11);
            *(uint32_t*)&g_S[srow0 + (size_t)rA * SEQ + kt * 64 + cc]       = *(uint32_t*)&p0;
            *(uint32_t*)&g_S[srow0 + (size_t)(rA + 8) * SEQ + kt * 64 + cc] = *(uint32_t*)&p1;
        }
    }
    rm0 = fmaxf(rm0, __shfl_xor_sync(0xFFFFFFFFu, rm0, 1));
    rm0 = fmaxf(rm0, __shfl_xor_sync(0xFFFFFFFFu, rm0, 2));
    rm1 = fmaxf(rm1, __shfl_xor_sync(0xFFFFFFFFu, rm1, 1));
    rm1 = fmaxf(rm1, __shfl_xor_sync(0xFFFFFFFFu, rm1, 2));
    if ((lane & 3) == 0) {
        mrow[rA]     = rm0;
        mrow[rA + 8] = rm1;
    }
    bar_sync(barid);

    // ====== PHASE 2: e via LUT (bitwise == expf path); L = bf16(sum_f32 e) ==
    for (int rb = 0; rb < 64; rb += 32) {
        const int r = rb + (wtid >> 2), seg = wtid & 3;
        unsigned short* rowp = (unsigned short*)&g_S[srow0 + (size_t)r * SEQ];
        const float m = mrow[r];
        float part = 0.f;
        for (int c = seg; c < len; c += 4) {
            float s = __bfloat162float(__ushort_as_bfloat16(rowp[c]));
            unsigned short tb = __bfloat16_as_ushort(__float2bfloat16(s - m));
            unsigned short eb = g_LUT[tb];
            part += __bfloat162float(__ushort_as_bfloat16(eb));
            rowp[c] = eb;
        }
        psum[r * 4 + seg] = part;
    }
    bar_sync(barid);
    if (wtid < 64) {
        float L32 = ((psum[wtid * 4 + 0] + psum[wtid * 4 + 1]) +
                      psum[wtid * 4 + 2]) + psum[wtid * 4 + 3];
        Lrow[wtid] = bf16r(L32);
    }
    bar_sync(barid);

    // ================= PHASE 3: p = bf16(e * (1/L)) -> A-frags, O = P @ V ==
    const float rL0 = 1.0f / Lrow[rA];
    const float rL1 = 1.0f / Lrow[rA + 8];
    const size_t srA = srow0 + (size_t)rA * SEQ;
    const size_t srB = srow0 + (size_t)(rA + 8) * SEQ;

    float o[8][4];
    #pragma unroll
    for (int nt = 0; nt < 8; nt++)
        #pragma unroll
        for (int i = 0; i < 4; i++) o[nt][i] = 0.f;

    stage_tile(kvb0, Vh, wtid);
    cp_commit();

    for (int kt = 0; kt <= qt; kt++) {
        cp_wait0();
        bar_sync(barid);
        const uint32_t kvb = (kt & 1) ? kvb1 : kvb0;
        if (kt < qt) {
            stage_tile((kt & 1) ? kvb0 : kvb1, Vh + (size_t)(kt + 1) * 64 * HD, wtid);
            cp_commit();
        }

        uint32_t pa[4][4];
        #pragma unroll
        for (int ks = 0; ks < 4; ks++) {
            const int col = kt * 64 + ks * 16 + (lane & 3) * 2;
            #pragma unroll
            for (int half = 0; half < 2; half++) {
                uint32_t sA = *(const uint32_t*)&g_S[srA + col + half * 8];
                uint32_t sB = *(const uint32_t*)&g_S[srB + col + half * 8];
                __nv_bfloat162 eA = *(__nv_bfloat162*)&sA;
                __nv_bfloat162 eB = *(__nv_bfloat162*)&sB;
                __nv_bfloat162 fA, fB;
                fA.x = __float2bfloat16(__bfloat162float(eA.x) * rL0);
                fA.y = __float2bfloat16(__bfloat162float(eA.y) * rL0);
                fB.x = __float2bfloat16(__bfloat162float(eB.x) * rL1);
                fB.y = __float2bfloat16(__bfloat162float(eB.y) * rL1);
                pa[ks][half * 2 + 0] = *(uint32_t*)&fA;
                pa[ks][half * 2 + 1] = *(uint32_t*)&fB;
            }
        }

        #pragma unroll
        for (int nt = 0; nt < 8; nt++) {
            #pragma unroll
            for (int ks = 0; ks < 4; ks++) {
                int l2 = lane & 15;
                uint32_t addr = kvb + (uint32_t)((ks * 16 + l2) * 144 + nt * 16);
                uint32_t b0, b1;
                ldsm_x2_t(b0, b1, addr);
                mma16816(o[nt][0], o[nt][1], o[nt][2], o[nt][3],
                         pa[ks][0], pa[ks][1], pa[ks][2], pa[ks][3], b0, b1);
            }
        }
    }

    const int qg0 = qt * 64;
    #pragma unroll
    for (int nt = 0; nt < 8; nt++) {
        const int colb = h * 64 + nt * 8 + (lane & 3) * 2;
        float2 vA = make_float2(bf16r(o[nt][0]), bf16r(o[nt][1]));
        float2 vB = make_float2(bf16r(o[nt][2]), bf16r(o[nt][3]));
        *(float2*)&g_attn[(size_t)(qg0 + rA) * EMB + colb]     = vA;
        *(float2*)&g_attn[(size_t)(qg0 + rA + 8) * EMB + colb] = vB;
    }
}

// per-WG smem partition: Qs 9216 B, KV2 18432 B, mrow 256, Lrow 256, psum 1024
#define WG_SMEM (9216 + 18432 + 256 + 256 + 1024)   // 29184 B

__global__ __launch_bounds__(256) void attn_kernel()
{
    extern __shared__ char asm_smem[];
    const int wg   = threadIdx.x >> 7;     // 0 or 1
    const int wtid = threadIdx.x & 127;

    char* base = asm_smem + wg * WG_SMEM;
    __nv_bfloat16* Qs  = (__nv_bfloat16*)base;
    __nv_bfloat16* KV2 = (__nv_bfloat16*)(base + 9216);
    float* mrow = (float*)(base + 9216 + 18432);
    float* Lrow = mrow + 64;
    float* psum = Lrow + 64;

    const int h  = blockIdx.y;
    const int qt = wg ? (31 - (int)blockIdx.x) : (int)blockIdx.x;
    attn_qtile(qt, h, Qs, KV2, mrow, Lrow, psum, wtid, wg + 1);
}

// ---------------------------------------------------------------------------
// Output projection, 2xTF32 — EXACT round-7/9/11 version (validated).
// ---------------------------------------------------------------------------
#define ASTR 36
#define BSTR 136

__global__ __launch_bounds__(256) void out_proj_tf32(
    const float* __restrict__ Wo, const float* __restrict__ bo,
    float* __restrict__ outp)
{
    extern __shared__ uint32_t dsm[];
    uint32_t* Ah = dsm;                    // [128][ASTR]
    uint32_t* Bh = Ah + 128 * ASTR;        // [32][BSTR]
    uint32_t* Bl = Bh + 32 * BSTR;

    const int tid = threadIdx.x, lane = tid & 31, warp = tid >> 5;
    const int wm = warp >> 2, wn = warp & 3;
    const int g = lane >> 2, t = lane & 3;
    const int bM = blockIdx.y * 128, bN = blockIdx.x * 128;

    float acc[4][4][4] = {};

    for (int k0 = 0; k0 < EMB; k0 += 32) {
        #pragma unroll
        for (int u = 0; u < 4; u++) {
            int idx = tid + u * 256;
            int row = idx >> 3, c4 = (idx & 7) * 4;
            float4 v = *(const float4*)(g_attn + (size_t)(bM + row) * EMB + k0 + c4);
            uint4 h;
            h.x = f2tf32(v.x); h.y = f2tf32(v.y);
            h.z = f2tf32(v.z); h.w = f2tf32(v.w);
            *(uint4*)&Ah[row * ASTR + c4] = h;
        }
        #pragma unroll
        for (int u = 0; u < 4; u++) {
            int idx = tid + u * 256;
            int kr = idx >> 5, c4 = (idx & 31) * 4;
            float4 v = *(const float4*)(Wo + (size_t)(k0 + kr) * EMB + bN + c4);
            uint4 h, l;
            h.x = f2tf32(v.x); l.x = f2tf32(v.x - __uint_as_float(h.x));
            h.y = f2tf32(v.y); l.y = f2tf32(v.y - __uint_as_float(h.y));
            h.z = f2tf32(v.z); l.z = f2tf32(v.z - __uint_as_float(h.z));
            h.w = f2tf32(v.w); l.w = f2tf32(v.w - __uint_as_float(h.w));
            *(uint4*)&Bh[kr * BSTR + c4] = h;
            *(uint4*)&Bl[kr * BSTR + c4] = l;
        }
        __syncthreads();

        #pragma unroll
        for (int ks = 0; ks < 4; ks++) {
            uint32_t ah[4][4], bh[4][2], bl[4][2];
            #pragma unroll
            for (int mi = 0; mi < 4; mi++) {
                int base = (wm * 64 + mi * 16 + g) * ASTR + ks * 8 + t;
                ah[mi][0] = Ah[base];
                ah[mi][1] = Ah[base + 8 * ASTR];
                ah[mi][2] = Ah[base + 4];
                ah[mi][3] = Ah[base + 8 * ASTR + 4];
            }
            #pragma unroll
            for (int nj = 0; nj < 4; nj++) {
                int base = (ks * 8 + t) * BSTR + wn * 32 + nj * 8 + g;
                bh[nj][0] = Bh[base];
                bh[nj][1] = Bh[base + 4 * BSTR];
                bl[nj][0] = Bl[base];
                bl[nj][1] = Bl[base + 4 * BSTR];
            }
            #pragma unroll
            for (int mi = 0; mi < 4; mi++)
                #pragma unroll
                for (int nj = 0; nj < 4; nj++) {
                    mma_tf32(acc[mi][nj], ah[mi], bh[nj]);
                    mma_tf32(acc[mi][nj], ah[mi], bl[nj]);
                }
        }
        __syncthreads();
    }

    #pragma unroll
    for (int mi = 0; mi < 4; mi++) {
        #pragma unroll
        for (int nj = 0; nj < 4; nj++) {
            int m0r = bM + wm * 64 + mi * 16 + g;
            int n   = bN + wn * 32 + nj * 8 + t * 2;
            float b0 = bo[n], b1 = bo[n + 1];
            float2 v0 = make_float2(acc[mi][nj][0] + b0, acc[mi][nj][1] + b1);
            float2 v1 = make_float2(acc[mi][nj][2] + b0, acc[mi][nj][3] + b1);
            *(float2*)&outp[(size_t)m0r * EMB + n]       = v0;
            *(float2*)&outp[(size_t)(m0r + 8) * EMB + n] = v1;
        }
    }
}

// ---------------------------------------------------------------------------

extern "C" void kernel_launch(void* const* d_in, const int* in_sizes, int n_in,
                              void* d_out, int out_size)
{
    const float* x  = (const float*)d_in[0];
    const float* Wq = (const float*)d_in[1];
    const float* bq = (const float*)d_in[2];
    const float* Wk = (const float*)d_in[3];
    const float* bk = (const float*)d_in[4];
    const float* Wv = (const float*)d_in[5];
    const float* bv = (const float*)d_in[6];
    const float* Wo = (const float*)d_in[7];
    const float* bo = (const float*)d_in[8];
    float* out = (float*)d_out;

    const int attn_smem = 2 * WG_SMEM;                            // 58368 B
    const int outp_smem = (128 * ASTR + 32 * BSTR * 2) * 4;       // 53248 B
    cudaFuncSetAttribute(attn_kernel,
                         cudaFuncAttributeMaxDynamicSharedMemorySize, attn_smem);
    cudaFuncSetAttribute(out_proj_tf32,
                         cudaFuncAttributeMaxDynamicSharedMemorySize, outp_smem);

    fill_lut<<<256, 256>>>();
    proj_qkv_kernel<<<dim3(EMB / 128, SEQ / 128, 3), 256>>>(x, Wq, bq, Wk, bk, Wv, bv);
    attn_kernel<<<dim3(16, NH), 256, attn_smem>>>();
    out_proj_tf32<<<dim3(EMB / 128, SEQ / 128), 256, outp_smem>>>(Wo, bo, out);
}

// round 13
// speedup vs baseline: 1.1776x; 1.1776x over previous
#include <cuda_runtime.h>
#include <cuda_bf16.h>
#include <math.h>
#include <stdint.h>

#define SEQ 2048
#define EMB 1024
#define NH  16
#define HD  64

// Scratch (device globals — no allocation allowed)
__device__ __nv_bfloat16 g_Q[NH * SEQ * HD];
__device__ __nv_bfloat16 g_K[NH * SEQ * HD];
__device__ __nv_bfloat16 g_V[NH * SEQ * HD];
// g_S: TILED layout [NH][32 qt][32 kt][64*64], scores then exp values
__device__ __nv_bfloat16 g_S[(size_t)NH * SEQ * SEQ];
__device__ float g_attn[SEQ * EMB];

__device__ __forceinline__ float bf16r(float v) {
    return __bfloat162float(__float2bfloat16(v));
}
__device__ __forceinline__ uint32_t f2tf32(float x) {
    uint32_t r;
    asm("cvt.rna.tf32.f32 %0, %1;" : "=r"(r) : "f"(x));
    return r;
}

// ---------------- mma.sync helpers ----------------
__device__ __forceinline__ uint32_t smem_u32(const void* p) {
    return (uint32_t)__cvta_generic_to_shared(p);
}
__device__ __forceinline__ void ldsm_x4(uint32_t& a0, uint32_t& a1,
                                        uint32_t& a2, uint32_t& a3, uint32_t addr) {
    asm volatile("ldmatrix.sync.aligned.m8n8.x4.shared.b16 {%0,%1,%2,%3}, [%4];\n"
                 : "=r"(a0), "=r"(a1), "=r"(a2), "=r"(a3) : "r"(addr));
}
__device__ __forceinline__ void ldsm_x2(uint32_t& b0, uint32_t& b1, uint32_t addr) {
    asm volatile("ldmatrix.sync.aligned.m8n8.x2.shared.b16 {%0,%1}, [%2];\n"
                 : "=r"(b0), "=r"(b1) : "r"(addr));
}
__device__ __forceinline__ void ldsm_x2_t(uint32_t& b0, uint32_t& b1, uint32_t addr) {
    asm volatile("ldmatrix.sync.aligned.m8n8.x2.trans.shared.b16 {%0,%1}, [%2];\n"
                 : "=r"(b0), "=r"(b1) : "r"(addr));
}
__device__ __forceinline__ void mma16816(float& d0, float& d1, float& d2, float& d3,
                                         uint32_t a0, uint32_t a1, uint32_t a2, uint32_t a3,
                                         uint32_t b0, uint32_t b1) {
    asm volatile("mma.sync.aligned.m16n8k16.row.col.f32.bf16.bf16.f32 "
                 "{%0,%1,%2,%3},{%4,%5,%6,%7},{%8,%9},{%0,%1,%2,%3};\n"
                 : "+f"(d0), "+f"(d1), "+f"(d2), "+f"(d3)
                 : "r"(a0), "r"(a1), "r"(a2), "r"(a3), "r"(b0), "r"(b1));
}
__device__ __forceinline__ void mma_tf32(float* d, const uint32_t* a,
                                         const uint32_t* b) {
    asm volatile("mma.sync.aligned.m16n8k8.row.col.f32.tf32.tf32.f32 "
                 "{%0,%1,%2,%3},{%4,%5,%6,%7},{%8,%9},{%0,%1,%2,%3};\n"
                 : "+f"(d[0]), "+f"(d[1]), "+f"(d[2]), "+f"(d[3])
                 : "r"(a[0]), "r"(a[1]), "r"(a[2]), "r"(a[3]), "r"(b[0]), "r"(b[1]));
}

// ---------------- cp.async helpers ----------------
__device__ __forceinline__ void cp_async16(uint32_t smem_addr, const void* gptr) {
    asm volatile("cp.async.cg.shared.global [%0], [%1], 16;\n"
                 :: "r"(smem_addr), "l"(gptr));
}
__device__ __forceinline__ void cp_commit() {
    asm volatile("cp.async.commit_group;\n" ::: "memory");
}
__device__ __forceinline__ void cp_wait0() {
    asm volatile("cp.async.wait_group 0;\n" ::: "memory");
}
__device__ __forceinline__ void bar_sync(int id) {
    asm volatile("bar.sync %0, 128;\n" :: "r"(id) : "memory");
}

// ---------------------------------------------------------------------------
// Fused QKV projection — EXACT round-11 version (sequential-K FFMA, Kc=8,
// double-buffered smem; at the FFMA-pipe roofline).
// ---------------------------------------------------------------------------
__global__ __launch_bounds__(256) void proj_qkv_kernel(
    const float* __restrict__ x,
    const float* __restrict__ Wq, const float* __restrict__ bq,
    const float* __restrict__ Wk, const float* __restrict__ bk,
    const float* __restrict__ Wv, const float* __restrict__ bv)
{
    const float* W; const float* bias; __nv_bfloat16* out;
    if (blockIdx.z == 0)      { W = Wq; bias = bq; out = g_Q; }
    else if (blockIdx.z == 1) { W = Wk; bias = bk; out = g_K; }
    else                      { W = Wv; bias = bv; out = g_V; }

    __shared__ float As[2][8][128];
    __shared__ float Bs[2][8][128];
    const int tid = threadIdx.x;
    const int tx = tid & 15, ty = tid >> 4;
    const int bM = blockIdx.y * 128, bN = blockIdx.x * 128;

    const int ar = tid >> 1, ac = (tid & 1) * 4;
    const int br = tid >> 5, bc = (tid & 31) * 4;

    float acc[8][8] = {};

    float4 pa = *(const float4*)(x + (size_t)(bM + ar) * EMB + ac);
    float4 pb = *(const float4*)(W + (size_t)br * EMB + bN + bc);

    for (int k0 = 0; k0 < EMB; k0 += 8) {
        const int b = (k0 >> 3) & 1;
        As[b][ac + 0][ar] = pa.x; As[b][ac + 1][ar] = pa.y;
        As[b][ac + 2][ar] = pa.z; As[b][ac + 3][ar] = pa.w;
        *(float4*)&Bs[b][br][bc] = pb;
        __syncthreads();

        if (k0 + 8 < EMB) {
            pa = *(const float4*)(x + (size_t)(bM + ar) * EMB + k0 + 8 + ac);
            pb = *(const float4*)(W + (size_t)(k0 + 8 + br) * EMB + bN + bc);
        }

        #pragma unroll
        for (int kk = 0; kk < 8; kk++) {
            float a[8], bb[8];
            *(float4*)&a[0]  = *(float4*)&As[b][kk][ty * 8];
            *(float4*)&a[4]  = *(float4*)&As[b][kk][ty * 8 + 4];
            *(float4*)&bb[0] = *(float4*)&Bs[b][kk][tx * 8];
            *(float4*)&bb[4] = *(float4*)&Bs[b][kk][tx * 8 + 4];
            #pragma unroll
            for (int i = 0; i < 8; i++)
                #pragma unroll
                for (int j = 0; j < 8; j++)
                    acc[i][j] = fmaf(a[i], bb[j], acc[i][j]);
        }
    }

    #pragma unroll
    for (int i = 0; i < 8; i++) {
        int m = bM + ty * 8 + i;
        #pragma unroll
        for (int j = 0; j < 8; j++) {
            int n = bN + tx * 8 + j;
            float v = acc[i][j] + bias[n];
            out[(size_t)(n >> 6) * SEQ * HD + (size_t)m * HD + (n & 63)] =
                __float2bfloat16(v);
        }
    }
}

// ---------------------------------------------------------------------------
// Causal attention — round-11 math (bit-safe), g_S in TILED layout
// [h][qt][kt][64x64] so every g_S access is 128B-row dense. Values and all
// summation orders identical to the passing kernels.
// ---------------------------------------------------------------------------
__device__ __forceinline__ void stage_tile(uint32_t dst, const __nv_bfloat16* src,
                                           int wtid) {
    #pragma unroll
    for (int u = 0; u < 4; u++) {
        int idx = wtid + u * 128;
        int r = idx >> 3, s = idx & 7;
        cp_async16(dst + (uint32_t)((r * 72 + s * 8) * 2), src + r * 64 + s * 8);
    }
}

__device__ void attn_qtile(
    int qt, int h, __nv_bfloat16* Qs, __nv_bfloat16* KV2,
    float* mrow, float* Lrow, float* psum, int wtid, int barid)
{
    const int lane = wtid & 31;
    const int warp = wtid >> 5;
    const int r0   = warp * 16;

    const size_t qbase = ((size_t)h * SEQ + (size_t)qt * 64) * HD;
    const size_t tile0 = (((size_t)h * 32 + qt) * 32) * 4096;  // kt-tile base
    const __nv_bfloat16* Kh = g_K + (size_t)h * SEQ * HD;
    const __nv_bfloat16* Vh = g_V + (size_t)h * SEQ * HD;

    const uint32_t kvb0 = smem_u32(KV2);
    const uint32_t kvb1 = kvb0 + 64 * 72 * 2;

    for (int idx = wtid; idx < 64 * 8; idx += 128) {
        int r = idx >> 3, s = idx & 7;
        *(uint4*)&Qs[r * 72 + s * 8] = *(const uint4*)&g_Q[qbase + r * 64 + s * 8];
    }
    bar_sync(barid);

    uint32_t aq[4][4];
    {
        const uint32_t qb = smem_u32(Qs);
        #pragma unroll
        for (int ks = 0; ks < 4; ks++) {
            uint32_t addr = qb +
                (uint32_t)((r0 + (lane & 7) + ((lane >> 3) & 1) * 8) * 144 +
                           ((lane >> 4) * 16) + ks * 32);
            ldsm_x4(aq[ks][0], aq[ks][1], aq[ks][2], aq[ks][3], addr);
        }
    }

    // ================= PHASE 1: S -> g_S tiles, running row max ============
    float rm0 = -INFINITY, rm1 = -INFINITY;
    const int rA = r0 + (lane >> 2);

    stage_tile(kvb0, Kh, wtid);
    cp_commit();

    for (int kt = 0; kt <= qt; kt++) {
        cp_wait0();
        bar_sync(barid);
        const uint32_t kvb = (kt & 1) ? kvb1 : kvb0;
        if (kt < qt) {
            stage_tile((kt & 1) ? kvb0 : kvb1, Kh + (size_t)(kt + 1) * 64 * HD, wtid);
            cp_commit();
        }

        const size_t tb = tile0 + (size_t)kt * 4096;
        const bool diag = (kt == qt);
        #pragma unroll
        for (int nt = 0; nt < 8; nt++) {
            float c0 = 0.f, c1 = 0.f, c2 = 0.f, c3 = 0.f;
            #pragma unroll
            for (int ks = 0; ks < 4; ks++) {
                int l2 = lane & 15;
                uint32_t addr = kvb +
                    (uint32_t)((nt * 8 + (l2 & 7)) * 144 + (l2 >> 3) * 16 + ks * 32);
                uint32_t b0, b1;
                ldsm_x2(b0, b1, addr);
                mma16816(c0, c1, c2, c3,
                         aq[ks][0], aq[ks][1], aq[ks][2], aq[ks][3], b0, b1);
            }
            const int cc = nt * 8 + (lane & 3) * 2;
            float s00 = bf16r(c0) * 0.5f;
            float s01 = bf16r(c1) * 0.5f;
            float s10 = bf16r(c2) * 0.5f;
            float s11 = bf16r(c3) * 0.5f;
            if (diag) {
                if (cc     > rA)     s00 = -INFINITY;
                if (cc + 1 > rA)     s01 = -INFINITY;
                if (cc     > rA + 8) s10 = -INFINITY;
                if (cc + 1 > rA + 8) s11 = -INFINITY;
            }
            rm0 = fmaxf(rm0, fmaxf(s00, s01));
            rm1 = fmaxf(rm1, fmaxf(s10, s11));
            __nv_bfloat162 p0; p0.x = __float2bfloat16(s00); p0.y = __float2bfloat16(s01);
            __nv_bfloat162 p1; p1.x = __float2bfloat16(s10); p1.y = __float2bfloat16(s11);
            *(uint32_t*)&g_S[tb + (size_t)rA * 64 + cc]       = *(uint32_t*)&p0;
            *(uint32_t*)&g_S[tb + (size_t)(rA + 8) * 64 + cc] = *(uint32_t*)&p1;
        }
    }
    rm0 = fmaxf(rm0, __shfl_xor_sync(0xFFFFFFFFu, rm0, 1));
    rm0 = fmaxf(rm0, __shfl_xor_sync(0xFFFFFFFFu, rm0, 2));
    rm1 = fmaxf(rm1, __shfl_xor_sync(0xFFFFFFFFu, rm1, 1));
    rm1 = fmaxf(rm1, __shfl_xor_sync(0xFFFFFFFFu, rm1, 2));
    if ((lane & 3) == 0) {
        mrow[rA]     = rm0;
        mrow[rA + 8] = rm1;
    }
    bar_sync(barid);

    // ====== PHASE 2: e -> g_S (same value/order chain as round 11) =========
    for (int rb = 0; rb < 64; rb += 32) {
        const int r = rb + (wtid >> 2), seg = wtid & 3;
        const float m = mrow[r];
        float part = 0.f;
        for (int ktt = 0; ktt <= qt; ktt++) {
            __nv_bfloat16* tp = &g_S[tile0 + (size_t)ktt * 4096 + (size_t)r * 64];
            #pragma unroll 4
            for (int c = seg; c < 64; c += 4) {
                float s = __bfloat162float(tp[c]);
                float t = bf16r(s - m);
                float e = bf16r(expf(t));
                part += e;
                tp[c] = __float2bfloat16(e);
            }
        }
        psum[r * 4 + seg] = part;
    }
    bar_sync(barid);
    if (wtid < 64) {
        float L32 = ((psum[wtid * 4 + 0] + psum[wtid * 4 + 1]) +
                      psum[wtid * 4 + 2]) + psum[wtid * 4 + 3];
        Lrow[wtid] = bf16r(L32);
    }
    bar_sync(barid);

    // ================= PHASE 3: p = bf16(e * (1/L)), O = P @ V =============
    const float rL0 = 1.0f / Lrow[rA];
    const float rL1 = 1.0f / Lrow[rA + 8];

    float o[8][4];
    #pragma unroll
    for (int nt = 0; nt < 8; nt++)
        #pragma unroll
        for (int i = 0; i < 4; i++) o[nt][i] = 0.f;

    stage_tile(kvb0, Vh, wtid);
    cp_commit();

    for (int kt = 0; kt <= qt; kt++) {
        cp_wait0();
        bar_sync(barid);
        const uint32_t kvb = (kt & 1) ? kvb1 : kvb0;
        if (kt < qt) {
            stage_tile((kt & 1) ? kvb0 : kvb1, Vh + (size_t)(kt + 1) * 64 * HD, wtid);
            cp_commit();
        }

        const size_t tb  = tile0 + (size_t)kt * 4096;
        const size_t rowA = tb + (size_t)rA * 64;
        const size_t rowB = tb + (size_t)(rA + 8) * 64;

        uint32_t pa[4][4];
        #pragma unroll
        for (int ks = 0; ks < 4; ks++) {
            const int col = ks * 16 + (lane & 3) * 2;   // within-tile column
            #pragma unroll
            for (int half = 0; half < 2; half++) {
                uint32_t sA = *(const uint32_t*)&g_S[rowA + col + half * 8];
                uint32_t sB = *(const uint32_t*)&g_S[rowB + col + half * 8];
                __nv_bfloat162 eA = *(__nv_bfloat162*)&sA;
                __nv_bfloat162 eB = *(__nv_bfloat162*)&sB;
                __nv_bfloat162 fA, fB;
                fA.x = __float2bfloat16(__bfloat162float(eA.x) * rL0);
                fA.y = __float2bfloat16(__bfloat162float(eA.y) * rL0);
                fB.x = __float2bfloat16(__bfloat162float(eB.x) * rL1);
                fB.y = __float2bfloat16(__bfloat162float(eB.y) * rL1);
                pa[ks][half * 2 + 0] = *(uint32_t*)&fA;
                pa[ks][half * 2 + 1] = *(uint32_t*)&fB;
            }
        }

        #pragma unroll
        for (int nt = 0; nt < 8; nt++) {
            #pragma unroll
            for (int ks = 0; ks < 4; ks++) {
                int l2 = lane & 15;
                uint32_t addr = kvb + (uint32_t)((ks * 16 + l2) * 144 + nt * 16);
                uint32_t b0, b1;
                ldsm_x2_t(b0, b1, addr);
                mma16816(o[nt][0], o[nt][1], o[nt][2], o[nt][3],
                         pa[ks][0], pa[ks][1], pa[ks][2], pa[ks][3], b0, b1);
            }
        }
    }

    const int qg0 = qt * 64;
    #pragma unroll
    for (int nt = 0; nt < 8; nt++) {
        const int colb = h * 64 + nt * 8 + (lane & 3) * 2;
        float2 vA = make_float2(bf16r(o[nt][0]), bf16r(o[nt][1]));
        float2 vB = make_float2(bf16r(o[nt][2]), bf16r(o[nt][3]));
        *(float2*)&g_attn[(size_t)(qg0 + rA) * EMB + colb]     = vA;
        *(float2*)&g_attn[(size_t)(qg0 + rA + 8) * EMB + colb] = vB;
    }
}

// per-WG smem partition: Qs 9216 B, KV2 18432 B, mrow 256, Lrow 256, psum 1024
#define WG_SMEM (9216 + 18432 + 256 + 256 + 1024)   // 29184 B

__global__ __launch_bounds__(256) void attn_kernel()
{
    extern __shared__ char asm_smem[];
    const int wg   = threadIdx.x >> 7;     // 0 or 1
    const int wtid = threadIdx.x & 127;

    char* base = asm_smem + wg * WG_SMEM;
    __nv_bfloat16* Qs  = (__nv_bfloat16*)base;
    __nv_bfloat16* KV2 = (__nv_bfloat16*)(base + 9216);
    float* mrow = (float*)(base + 9216 + 18432);
    float* Lrow = mrow + 64;
    float* psum = Lrow + 64;

    const int h  = blockIdx.y;
    const int qt = wg ? (31 - (int)blockIdx.x) : (int)blockIdx.x;
    attn_qtile(qt, h, Qs, KV2, mrow, Lrow, psum, wtid, wg + 1);
}

// ---------------------------------------------------------------------------
// Output projection, 2xTF32, 64m x 128n tiles (grid 256) + register prefetch.
// Per-output arithmetic (ks order, hh then hl) identical to the validated
// round-7/9/11 kernel -> bit-safe.
// ---------------------------------------------------------------------------
#define ASTR 36
#define BSTR 136

__global__ __launch_bounds__(256) void out_proj_tf32(
    const float* __restrict__ Wo, const float* __restrict__ bo,
    float* __restrict__ outp)
{
    extern __shared__ uint32_t dsm[];
    uint32_t* Ah = dsm;                    // [64][ASTR]
    uint32_t* Bh = Ah + 64 * ASTR;         // [32][BSTR]
    uint32_t* Bl = Bh + 32 * BSTR;

    const int tid = threadIdx.x, lane = tid & 31, warp = tid >> 5;
    const int wm = warp >> 2, wn = warp & 3;   // wm 0-1 (32 rows), wn 0-3 (32 cols)
    const int g = lane >> 2, t = lane & 3;
    const int bM = blockIdx.y * 64, bN = blockIdx.x * 128;

    // staging coords
    const int a_row = tid >> 3, a_c = (tid & 7) * 4;          // A: 64x32, 2/thread
    const int a_row1 = (tid + 256) >> 3, a_c1 = ((tid + 256) & 7) * 4;
    // B: 32x128, 4/thread
    float acc[2][4][4] = {};

    float4 pa0 = *(const float4*)(g_attn + (size_t)(bM + a_row) * EMB + a_c);
    float4 pa1 = *(const float4*)(g_attn + (size_t)(bM + a_row1) * EMB + a_c1);
    float4 pb[4];
    #pragma unroll
    for (int u = 0; u < 4; u++) {
        int idx = tid + u * 256;
        pb[u] = *(const float4*)(Wo + (size_t)(idx >> 5) * EMB + bN + (idx & 31) * 4);
    }

    for (int k0 = 0; k0 < EMB; k0 += 32) {
        {
            uint4 h;
            h.x = f2tf32(pa0.x); h.y = f2tf32(pa0.y);
            h.z = f2tf32(pa0.z); h.w = f2tf32(pa0.w);
            *(uint4*)&Ah[a_row * ASTR + a_c] = h;
            h.x = f2tf32(pa1.x); h.y = f2tf32(pa1.y);
            h.z = f2tf32(pa1.z); h.w = f2tf32(pa1.w);
            *(uint4*)&Ah[a_row1 * ASTR + a_c1] = h;
        }
        #pragma unroll
        for (int u = 0; u < 4; u++) {
            int idx = tid + u * 256;
            int kr = idx >> 5, c4 = (idx & 31) * 4;
            float4 v = pb[u];
            uint4 h, l;
            h.x = f2tf32(v.x); l.x = f2tf32(v.x - __uint_as_float(h.x));
            h.y = f2tf32(v.y); l.y = f2tf32(v.y - __uint_as_float(h.y));
            h.z = f2tf32(v.z); l.z = f2tf32(v.z - __uint_as_float(h.z));
            h.w = f2tf32(v.w); l.w = f2tf32(v.w - __uint_as_float(h.w));
            *(uint4*)&Bh[kr * BSTR + c4] = h;
            *(uint4*)&Bl[kr * BSTR + c4] = l;
        }
        __syncthreads();

        if (k0 + 32 < EMB) {
            pa0 = *(const float4*)(g_attn + (size_t)(bM + a_row) * EMB + k0 + 32 + a_c);
            pa1 = *(const float4*)(g_attn + (size_t)(bM + a_row1) * EMB + k0 + 32 + a_c1);
            #pragma unroll
            for (int u = 0; u < 4; u++) {
                int idx = tid + u * 256;
                pb[u] = *(const float4*)(Wo + (size_t)(k0 + 32 + (idx >> 5)) * EMB +
                                         bN + (idx & 31) * 4);
            }
        }

        #pragma unroll
        for (int ks = 0; ks < 4; ks++) {
            uint32_t ah[2][4], bh[4][2], bl[4][2];
            #pragma unroll
            for (int mi = 0; mi < 2; mi++) {
                int base = (wm * 32 + mi * 16 + g) * ASTR + ks * 8 + t;
                ah[mi][0] = Ah[base];
                ah[mi][1] = Ah[base + 8 * ASTR];
                ah[mi][2] = Ah[base + 4];
                ah[mi][3] = Ah[base + 8 * ASTR + 4];
            }
            #pragma unroll
            for (int nj = 0; nj < 4; nj++) {
                int base = (ks * 8 + t) * BSTR + wn * 32 + nj * 8 + g;
                bh[nj][0] = Bh[base];
                bh[nj][1] = Bh[base + 4 * BSTR];
                bl[nj][0] = Bl[base];
                bl[nj][1] = Bl[base + 4 * BSTR];
            }
            #pragma unroll
            for (int mi = 0; mi < 2; mi++)
                #pragma unroll
                for (int nj = 0; nj < 4; nj++) {
                    mma_tf32(acc[mi][nj], ah[mi], bh[nj]);
                    mma_tf32(acc[mi][nj], ah[mi], bl[nj]);
                }
        }
        __syncthreads();
    }

    #pragma unroll
    for (int mi = 0; mi < 2; mi++) {
        #pragma unroll
        for (int nj = 0; nj < 4; nj++) {
            int m0r = bM + wm * 32 + mi * 16 + g;
            int n   = bN + wn * 32 + nj * 8 + t * 2;
            float b0 = bo[n], b1 = bo[n + 1];
            float2 v0 = make_float2(acc[mi][nj][0] + b0, acc[mi][nj][1] + b1);
            float2 v1 = make_float2(acc[mi][nj][2] + b0, acc[mi][nj][3] + b1);
            *(float2*)&outp[(size_t)m0r * EMB + n]       = v0;
            *(float2*)&outp[(size_t)(m0r + 8) * EMB + n] = v1;
        }
    }
}

// ---------------------------------------------------------------------------

extern "C" void kernel_launch(void* const* d_in, const int* in_sizes, int n_in,
                              void* d_out, int out_size)
{
    const float* x  = (const float*)d_in[0];
    const float* Wq = (const float*)d_in[1];
    const float* bq = (const float*)d_in[2];
    const float* Wk = (const float*)d_in[3];
    const float* bk = (const float*)d_in[4];
    const float* Wv = (const float*)d_in[5];
    const float* bv = (const float*)d_in[6];
    const float* Wo = (const float*)d_in[7];
    const float* bo = (const float*)d_in[8];
    float* out = (float*)d_out;

    const int attn_smem = 2 * WG_SMEM;                            // 58368 B
    const int outp_smem = (64 * ASTR + 32 * BSTR * 2) * 4;        // 44032 B
    cudaFuncSetAttribute(attn_kernel,
                         cudaFuncAttributeMaxDynamicSharedMemorySize, attn_smem);
    cudaFuncSetAttribute(out_proj_tf32,
                         cudaFuncAttributeMaxDynamicSharedMemorySize, outp_smem);

    proj_qkv_kernel<<<dim3(EMB / 128, SEQ / 128, 3), 256>>>(x, Wq, bq, Wk, bk, Wv, bv);
    attn_kernel<<<dim3(16, NH), 256, attn_smem>>>();
    out_proj_tf32<<<dim3(EMB / 128, SEQ / 64), 256, outp_smem>>>(Wo, bo, out);
}

// round 14
// speedup vs baseline: 1.1898x; 1.0104x over previous
#include <cuda_runtime.h>
#include <cuda_bf16.h>
#include <math.h>
#include <stdint.h>

#define SEQ 2048
#define EMB 1024
#define NH  16
#define HD  64

typedef unsigned long long u64;

// Scratch (device globals — no allocation allowed)
__device__ __nv_bfloat16 g_Q[NH * SEQ * HD];
__device__ __nv_bfloat16 g_K[NH * SEQ * HD];
__device__ __nv_bfloat16 g_V[NH * SEQ * HD];
// g_S: TILED layout [NH][32 qt][32 kt][64*64], scores then exp values
__device__ __nv_bfloat16 g_S[(size_t)NH * SEQ * SEQ];
__device__ float g_attn[SEQ * EMB];

__device__ __forceinline__ float bf16r(float v) {
    return __bfloat162float(__float2bfloat16(v));
}
__device__ __forceinline__ uint32_t f2tf32(float x) {
    uint32_t r;
    asm("cvt.rna.tf32.f32 %0, %1;" : "=r"(r) : "f"(x));
    return r;
}

// ---------------- packed f32x2 fma (Blackwell FFMA2) ----------------
// Each half is an independent fma.rn.f32 -> bitwise identical to scalar fmaf.
__device__ __forceinline__ void fma2(u64& d, u64 a, u64 b) {
    asm("fma.rn.f32x2 %0, %1, %2, %0;" : "+l"(d) : "l"(a), "l"(b));
}
__device__ __forceinline__ u64 bcast2(float v) {
    u64 r; asm("mov.b64 %0, {%1, %2};" : "=l"(r) : "f"(v), "f"(v)); return r;
}
__device__ __forceinline__ void unpack2(u64 p, float& lo, float& hi) {
    asm("mov.b64 {%0, %1}, %2;" : "=f"(lo), "=f"(hi) : "l"(p));
}

// ---------------- mma.sync helpers ----------------
__device__ __forceinline__ uint32_t smem_u32(const void* p) {
    return (uint32_t)__cvta_generic_to_shared(p);
}
__device__ __forceinline__ void ldsm_x4(uint32_t& a0, uint32_t& a1,
                                        uint32_t& a2, uint32_t& a3, uint32_t addr) {
    asm volatile("ldmatrix.sync.aligned.m8n8.x4.shared.b16 {%0,%1,%2,%3}, [%4];\n"
                 : "=r"(a0), "=r"(a1), "=r"(a2), "=r"(a3) : "r"(addr));
}
__device__ __forceinline__ void ldsm_x2(uint32_t& b0, uint32_t& b1, uint32_t addr) {
    asm volatile("ldmatrix.sync.aligned.m8n8.x2.shared.b16 {%0,%1}, [%2];\n"
                 : "=r"(b0), "=r"(b1) : "r"(addr));
}
__device__ __forceinline__ void ldsm_x2_t(uint32_t& b0, uint32_t& b1, uint32_t addr) {
    asm volatile("ldmatrix.sync.aligned.m8n8.x2.trans.shared.b16 {%0,%1}, [%2];\n"
                 : "=r"(b0), "=r"(b1) : "r"(addr));
}
__device__ __forceinline__ void mma16816(float& d0, float& d1, float& d2, float& d3,
                                         uint32_t a0, uint32_t a1, uint32_t a2, uint32_t a3,
                                         uint32_t b0, uint32_t b1) {
    asm volatile("mma.sync.aligned.m16n8k16.row.col.f32.bf16.bf16.f32 "
                 "{%0,%1,%2,%3},{%4,%5,%6,%7},{%8,%9},{%0,%1,%2,%3};\n"
                 : "+f"(d0), "+f"(d1), "+f"(d2), "+f"(d3)
                 : "r"(a0), "r"(a1), "r"(a2), "r"(a3), "r"(b0), "r"(b1));
}
__device__ __forceinline__ void mma_tf32(float* d, const uint32_t* a,
                                         const uint32_t* b) {
    asm volatile("mma.sync.aligned.m16n8k8.row.col.f32.tf32.tf32.f32 "
                 "{%0,%1,%2,%3},{%4,%5,%6,%7},{%8,%9},{%0,%1,%2,%3};\n"
                 : "+f"(d[0]), "+f"(d[1]), "+f"(d[2]), "+f"(d[3])
                 : "r"(a[0]), "r"(a[1]), "r"(a[2]), "r"(a[3]), "r"(b[0]), "r"(b[1]));
}

// ---------------- cp.async helpers ----------------
__device__ __forceinline__ void cp_async16(uint32_t smem_addr, const void* gptr) {
    asm volatile("cp.async.cg.shared.global [%0], [%1], 16;\n"
                 :: "r"(smem_addr), "l"(gptr));
}
__device__ __forceinline__ void cp_commit() {
    asm volatile("cp.async.commit_group;\n" ::: "memory");
}
__device__ __forceinline__ void cp_wait0() {
    asm volatile("cp.async.wait_group 0;\n" ::: "memory");
}
__device__ __forceinline__ void bar_sync(int id) {
    asm volatile("bar.sync %0, 128;\n" :: "r"(id) : "memory");
}

// ---------------------------------------------------------------------------
// Fused QKV projection — sequential-K FFMA chains packed two-wide with
// fma.rn.f32x2 (each half bitwise == scalar fmaf; per-chain order unchanged).
// Kc=8, double-buffered smem, register prefetch (round-11 structure).
// ---------------------------------------------------------------------------
__global__ __launch_bounds__(256) void proj_qkv_kernel(
    const float* __restrict__ x,
    const float* __restrict__ Wq, const float* __restrict__ bq,
    const float* __restrict__ Wk, const float* __restrict__ bk,
    const float* __restrict__ Wv, const float* __restrict__ bv)
{
    const float* W; const float* bias; __nv_bfloat16* out;
    if (blockIdx.z == 0)      { W = Wq; bias = bq; out = g_Q; }
    else if (blockIdx.z == 1) { W = Wk; bias = bk; out = g_K; }
    else                      { W = Wv; bias = bv; out = g_V; }

    __shared__ float As[2][8][128];
    __shared__ float Bs[2][8][128];
    const int tid = threadIdx.x;
    const int tx = tid & 15, ty = tid >> 4;
    const int bM = blockIdx.y * 128, bN = blockIdx.x * 128;

    const int ar = tid >> 1, ac = (tid & 1) * 4;
    const int br = tid >> 5, bc = (tid & 31) * 4;

    // acc2[i][jp] = (acc[i][2jp] , acc[i][2jp+1]) packed f32x2
    u64 acc2[8][4] = {};

    float4 pa = *(const float4*)(x + (size_t)(bM + ar) * EMB + ac);
    float4 pb = *(const float4*)(W + (size_t)br * EMB + bN + bc);

    for (int k0 = 0; k0 < EMB; k0 += 8) {
        const int b = (k0 >> 3) & 1;
        As[b][ac + 0][ar] = pa.x; As[b][ac + 1][ar] = pa.y;
        As[b][ac + 2][ar] = pa.z; As[b][ac + 3][ar] = pa.w;
        *(float4*)&Bs[b][br][bc] = pb;
        __syncthreads();

        if (k0 + 8 < EMB) {
            pa = *(const float4*)(x + (size_t)(bM + ar) * EMB + k0 + 8 + ac);
            pb = *(const float4*)(W + (size_t)(k0 + 8 + br) * EMB + bN + bc);
        }

        #pragma unroll
        for (int kk = 0; kk < 8; kk++) {
            float a[8];
            *(float4*)&a[0]  = *(float4*)&As[b][kk][ty * 8];
            *(float4*)&a[4]  = *(float4*)&As[b][kk][ty * 8 + 4];
            u64 bb2[4];
            bb2[0] = *(const u64*)&Bs[b][kk][tx * 8 + 0];
            bb2[1] = *(const u64*)&Bs[b][kk][tx * 8 + 2];
            bb2[2] = *(const u64*)&Bs[b][kk][tx * 8 + 4];
            bb2[3] = *(const u64*)&Bs[b][kk][tx * 8 + 6];
            #pragma unroll
            for (int i = 0; i < 8; i++) {
                u64 ai = bcast2(a[i]);
                #pragma unroll
                for (int jp = 0; jp < 4; jp++)
                    fma2(acc2[i][jp], ai, bb2[jp]);
            }
        }
    }

    #pragma unroll
    for (int i = 0; i < 8; i++) {
        int m = bM + ty * 8 + i;
        #pragma unroll
        for (int jp = 0; jp < 4; jp++) {
            float v0, v1;
            unpack2(acc2[i][jp], v0, v1);
            int n = bN + tx * 8 + jp * 2;
            float r0 = v0 + bias[n];
            float r1 = v1 + bias[n + 1];
            out[(size_t)(n >> 6) * SEQ * HD + (size_t)m * HD + (n & 63)] =
                __float2bfloat16(r0);
            out[(size_t)((n + 1) >> 6) * SEQ * HD + (size_t)m * HD + ((n + 1) & 63)] =
                __float2bfloat16(r1);
        }
    }
}

// ---------------------------------------------------------------------------
// Causal attention — byte-identical to round 13 (bit-safe, tiled g_S).
// ---------------------------------------------------------------------------
__device__ __forceinline__ void stage_tile(uint32_t dst, const __nv_bfloat16* src,
                                           int wtid) {
    #pragma unroll
    for (int u = 0; u < 4; u++) {
        int idx = wtid + u * 128;
        int r = idx >> 3, s = idx & 7;
        cp_async16(dst + (uint32_t)((r * 72 + s * 8) * 2), src + r * 64 + s * 8);
    }
}

__device__ void attn_qtile(
    int qt, int h, __nv_bfloat16* Qs, __nv_bfloat16* KV2,
    float* mrow, float* Lrow, float* psum, int wtid, int barid)
{
    const int lane = wtid & 31;
    const int warp = wtid >> 5;
    const int r0   = warp * 16;

    const size_t qbase = ((size_t)h * SEQ + (size_t)qt * 64) * HD;
    const size_t tile0 = (((size_t)h * 32 + qt) * 32) * 4096;  // kt-tile base
    const __nv_bfloat16* Kh = g_K + (size_t)h * SEQ * HD;
    const __nv_bfloat16* Vh = g_V + (size_t)h * SEQ * HD;

    const uint32_t kvb0 = smem_u32(KV2);
    const uint32_t kvb1 = kvb0 + 64 * 72 * 2;

    for (int idx = wtid; idx < 64 * 8; idx += 128) {
        int r = idx >> 3, s = idx & 7;
        *(uint4*)&Qs[r * 72 + s * 8] = *(const uint4*)&g_Q[qbase + r * 64 + s * 8];
    }
    bar_sync(barid);

    uint32_t aq[4][4];
    {
        const uint32_t qb = smem_u32(Qs);
        #pragma unroll
        for (int ks = 0; ks < 4; ks++) {
            uint32_t addr = qb +
                (uint32_t)((r0 + (lane & 7) + ((lane >> 3) & 1) * 8) * 144 +
                           ((lane >> 4) * 16) + ks * 32);
            ldsm_x4(aq[ks][0], aq[ks][1], aq[ks][2], aq[ks][3], addr);
        }
    }

    // ================= PHASE 1: S -> g_S tiles, running row max ============
    float rm0 = -INFINITY, rm1 = -INFINITY;
    const int rA = r0 + (lane >> 2);

    stage_tile(kvb0, Kh, wtid);
    cp_commit();

    for (int kt = 0; kt <= qt; kt++) {
        cp_wait0();
        bar_sync(barid);
        const uint32_t kvb = (kt & 1) ? kvb1 : kvb0;
        if (kt < qt) {
            stage_tile((kt & 1) ? kvb0 : kvb1, Kh + (size_t)(kt + 1) * 64 * HD, wtid);
            cp_commit();
        }

        const size_t tb = tile0 + (size_t)kt * 4096;
        const bool diag = (kt == qt);
        #pragma unroll
        for (int nt = 0; nt < 8; nt++) {
            float c0 = 0.f, c1 = 0.f, c2 = 0.f, c3 = 0.f;
            #pragma unroll
            for (int ks = 0; ks < 4; ks++) {
                int l2 = lane & 15;
                uint32_t addr = kvb +
                    (uint32_t)((nt * 8 + (l2 & 7)) * 144 + (l2 >> 3) * 16 + ks * 32);
                uint32_t b0, b1;
                ldsm_x2(b0, b1, addr);
                mma16816(c0, c1, c2, c3,
                         aq[ks][0], aq[ks][1], aq[ks][2], aq[ks][3], b0, b1);
            }
            const int cc = nt * 8 + (lane & 3) * 2;
            float s00 = bf16r(c0) * 0.5f;
            float s01 = bf16r(c1) * 0.5f;
            float s10 = bf16r(c2) * 0.5f;
            float s11 = bf16r(c3) * 0.5f;
            if (diag) {
                if (cc     > rA)     s00 = -INFINITY;
                if (cc + 1 > rA)     s01 = -INFINITY;
                if (cc     > rA + 8) s10 = -INFINITY;
                if (cc + 1 > rA + 8) s11 = -INFINITY;
            }
            rm0 = fmaxf(rm0, fmaxf(s00, s01));
            rm1 = fmaxf(rm1, fmaxf(s10, s11));
            __nv_bfloat162 p0; p0.x = __float2bfloat16(s00); p0.y = __float2bfloat16(s01);
            __nv_bfloat162 p1; p1.x = __float2bfloat16(s10); p1.y = __float2bfloat16(s11);
            *(uint32_t*)&g_S[tb + (size_t)rA * 64 + cc]       = *(uint32_t*)&p0;
            *(uint32_t*)&g_S[tb + (size_t)(rA + 8) * 64 + cc] = *(uint32_t*)&p1;
        }
    }
    rm0 = fmaxf(rm0, __shfl_xor_sync(0xFFFFFFFFu, rm0, 1));
    rm0 = fmaxf(rm0, __shfl_xor_sync(0xFFFFFFFFu, rm0, 2));
    rm1 = fmaxf(rm1, __shfl_xor_sync(0xFFFFFFFFu, rm1, 1));
    rm1 = fmaxf(rm1, __shfl_xor_sync(0xFFFFFFFFu, rm1, 2));
    if ((lane & 3) == 0) {
        mrow[rA]     = rm0;
        mrow[rA + 8] = rm1;
    }
    bar_sync(barid);

    // ====== PHASE 2: e -> g_S (same value/order chain) =====================
    for (int rb = 0; rb < 64; rb += 32) {
        const int r = rb + (wtid >> 2), seg = wtid & 3;
        const float m = mrow[r];
        float part = 0.f;
        for (int ktt = 0; ktt <= qt; ktt++) {
            __nv_bfloat16* tp = &g_S[tile0 + (size_t)ktt * 4096 + (size_t)r * 64];
            #pragma unroll 4
            for (int c = seg; c < 64; c += 4) {
                float s = __bfloat162float(tp[c]);
                float t = bf16r(s - m);
                float e = bf16r(expf(t));
                part += e;
                tp[c] = __float2bfloat16(e);
            }
        }
        psum[r * 4 + seg] = part;
    }
    bar_sync(barid);
    if (wtid < 64) {
        float L32 = ((psum[wtid * 4 + 0] + psum[wtid * 4 + 1]) +
                      psum[wtid * 4 + 2]) + psum[wtid * 4 + 3];
        Lrow[wtid] = bf16r(L32);
    }
    bar_sync(barid);

    // ================= PHASE 3: p = bf16(e * (1/L)), O = P @ V =============
    const float rL0 = 1.0f / Lrow[rA];
    const float rL1 = 1.0f / Lrow[rA + 8];

    float o[8][4];
    #pragma unroll
    for (int nt = 0; nt < 8; nt++)
        #pragma unroll
        for (int i = 0; i < 4; i++) o[nt][i] = 0.f;

    stage_tile(kvb0, Vh, wtid);
    cp_commit();

    for (int kt = 0; kt <= qt; kt++) {
        cp_wait0();
        bar_sync(barid);
        const uint32_t kvb = (kt & 1) ? kvb1 : kvb0;
        if (kt < qt) {
            stage_tile((kt & 1) ? kvb0 : kvb1, Vh + (size_t)(kt + 1) * 64 * HD, wtid);
            cp_commit();
        }

        const size_t tb  = tile0 + (size_t)kt * 4096;
        const size_t rowA = tb + (size_t)rA * 64;
        const size_t rowB = tb + (size_t)(rA + 8) * 64;

        uint32_t pa[4][4];
        #pragma unroll
        for (int ks = 0; ks < 4; ks++) {
            const int col = ks * 16 + (lane & 3) * 2;   // within-tile column
            #pragma unroll
            for (int half = 0; half < 2; half++) {
                uint32_t sA = *(const uint32_t*)&g_S[rowA + col + half * 8];
                uint32_t sB = *(const uint32_t*)&g_S[rowB + col + half * 8];
                __nv_bfloat162 eA = *(__nv_bfloat162*)&sA;
                __nv_bfloat162 eB = *(__nv_bfloat162*)&sB;
                __nv_bfloat162 fA, fB;
                fA.x = __float2bfloat16(__bfloat162float(eA.x) * rL0);
                fA.y = __float2bfloat16(__bfloat162float(eA.y) * rL0);
                fB.x = __float2bfloat16(__bfloat162float(eB.x) * rL1);
                fB.y = __float2bfloat16(__bfloat162float(eB.y) * rL1);
                pa[ks][half * 2 + 0] = *(uint32_t*)&fA;
                pa[ks][half * 2 + 1] = *(uint32_t*)&fB;
            }
        }

        #pragma unroll
        for (int nt = 0; nt < 8; nt++) {
            #pragma unroll
            for (int ks = 0; ks < 4; ks++) {
                int l2 = lane & 15;
                uint32_t addr = kvb + (uint32_t)((ks * 16 + l2) * 144 + nt * 16);
                uint32_t b0, b1;
                ldsm_x2_t(b0, b1, addr);
                mma16816(o[nt][0], o[nt][1], o[nt][2], o[nt][3],
                         pa[ks][0], pa[ks][1], pa[ks][2], pa[ks][3], b0, b1);
            }
        }
    }

    const int qg0 = qt * 64;
    #pragma unroll
    for (int nt = 0; nt < 8; nt++) {
        const int colb = h * 64 + nt * 8 + (lane & 3) * 2;
        float2 vA = make_float2(bf16r(o[nt][0]), bf16r(o[nt][1]));
        float2 vB = make_float2(bf16r(o[nt][2]), bf16r(o[nt][3]));
        *(float2*)&g_attn[(size_t)(qg0 + rA) * EMB + colb]     = vA;
        *(float2*)&g_attn[(size_t)(qg0 + rA + 8) * EMB + colb] = vB;
    }
}

// per-WG smem partition: Qs 9216 B, KV2 18432 B, mrow 256, Lrow 256, psum 1024
#define WG_SMEM (9216 + 18432 + 256 + 256 + 1024)   // 29184 B

__global__ __launch_bounds__(256) void attn_kernel()
{
    extern __shared__ char asm_smem[];
    const int wg   = threadIdx.x >> 7;     // 0 or 1
    const int wtid = threadIdx.x & 127;

    char* base = asm_smem + wg * WG_SMEM;
    __nv_bfloat16* Qs  = (__nv_bfloat16*)base;
    __nv_bfloat16* KV2 = (__nv_bfloat16*)(base + 9216);
    float* mrow = (float*)(base + 9216 + 18432);
    float* Lrow = mrow + 64;
    float* psum = Lrow + 64;

    const int h  = blockIdx.y;
    const int qt = wg ? (31 - (int)blockIdx.x) : (int)blockIdx.x;
    attn_qtile(qt, h, Qs, KV2, mrow, Lrow, psum, wtid, wg + 1);
}

// ---------------------------------------------------------------------------
// Output projection, 2xTF32, 64m x 128n tiles + register prefetch — EXACT
// round-13 version (validated).
// ---------------------------------------------------------------------------
#define ASTR 36
#define BSTR 136

__global__ __launch_bounds__(256) void out_proj_tf32(
    const float* __restrict__ Wo, const float* __restrict__ bo,
    float* __restrict__ outp)
{
    extern __shared__ uint32_t dsm[];
    uint32_t* Ah = dsm;                    // [64][ASTR]
    uint32_t* Bh = Ah + 64 * ASTR;         // [32][BSTR]
    uint32_t* Bl = Bh + 32 * BSTR;

    const int tid = threadIdx.x, lane = tid & 31, warp = tid >> 5;
    const int wm = warp >> 2, wn = warp & 3;
    const int g = lane >> 2, t = lane & 3;
    const int bM = blockIdx.y * 64, bN = blockIdx.x * 128;

    const int a_row = tid >> 3, a_c = (tid & 7) * 4;
    const int a_row1 = (tid + 256) >> 3, a_c1 = ((tid + 256) & 7) * 4;
    float acc[2][4][4] = {};

    float4 pa0 = *(const float4*)(g_attn + (size_t)(bM + a_row) * EMB + a_c);
    float4 pa1 = *(const float4*)(g_attn + (size_t)(bM + a_row1) * EMB + a_c1);
    float4 pb[4];
    #pragma unroll
    for (int u = 0; u < 4; u++) {
        int idx = tid + u * 256;
        pb[u] = *(const float4*)(Wo + (size_t)(idx >> 5) * EMB + bN + (idx & 31) * 4);
    }

    for (int k0 = 0; k0 < EMB; k0 += 32) {
        {
            uint4 h;
            h.x = f2tf32(pa0.x); h.y = f2tf32(pa0.y);
            h.z = f2tf32(pa0.z); h.w = f2tf32(pa0.w);
            *(uint4*)&Ah[a_row * ASTR + a_c] = h;
            h.x = f2tf32(pa1.x); h.y = f2tf32(pa1.y);
            h.z = f2tf32(pa1.z); h.w = f2tf32(pa1.w);
            *(uint4*)&Ah[a_row1 * ASTR + a_c1] = h;
        }
        #pragma unroll
        for (int u = 0; u < 4; u++) {
            int idx = tid + u * 256;
            int kr = idx >> 5, c4 = (idx & 31) * 4;
            float4 v = pb[u];
            uint4 h, l;
            h.x = f2tf32(v.x); l.x = f2tf32(v.x - __uint_as_float(h.x));
            h.y = f2tf32(v.y); l.y = f2tf32(v.y - __uint_as_float(h.y));
            h.z = f2tf32(v.z); l.z = f2tf32(v.z - __uint_as_float(h.z));
            h.w = f2tf32(v.w); l.w = f2tf32(v.w - __uint_as_float(h.w));
            *(uint4*)&Bh[kr * BSTR + c4] = h;
            *(uint4*)&Bl[kr * BSTR + c4] = l;
        }
        __syncthreads();

        if (k0 + 32 < EMB) {
            pa0 = *(const float4*)(g_attn + (size_t)(bM + a_row) * EMB + k0 + 32 + a_c);
            pa1 = *(const float4*)(g_attn + (size_t)(bM + a_row1) * EMB + k0 + 32 + a_c1);
            #pragma unroll
            for (int u = 0; u < 4; u++) {
                int idx = tid + u * 256;
                pb[u] = *(const float4*)(Wo + (size_t)(k0 + 32 + (idx >> 5)) * EMB +
                                         bN + (idx & 31) * 4);
            }
        }

        #pragma unroll
        for (int ks = 0; ks < 4; ks++) {
            uint32_t ah[2][4], bh[4][2], bl[4][2];
            #pragma unroll
            for (int mi = 0; mi < 2; mi++) {
                int base = (wm * 32 + mi * 16 + g) * ASTR + ks * 8 + t;
                ah[mi][0] = Ah[base];
                ah[mi][1] = Ah[base + 8 * ASTR];
                ah[mi][2] = Ah[base + 4];
                ah[mi][3] = Ah[base + 8 * ASTR + 4];
            }
            #pragma unroll
            for (int nj = 0; nj < 4; nj++) {
                int base = (ks * 8 + t) * BSTR + wn * 32 + nj * 8 + g;
                bh[nj][0] = Bh[base];
                bh[nj][1] = Bh[base + 4 * BSTR];
                bl[nj][0] = Bl[base];
                bl[nj][1] = Bl[base + 4 * BSTR];
            }
            #pragma unroll
            for (int mi = 0; mi < 2; mi++)
                #pragma unroll
                for (int nj = 0; nj < 4; nj++) {
                    mma_tf32(acc[mi][nj], ah[mi], bh[nj]);
                    mma_tf32(acc[mi][nj], ah[mi], bl[nj]);
                }
        }
        __syncthreads();
    }

    #pragma unroll
    for (int mi = 0; mi < 2; mi++) {
        #pragma unroll
        for (int nj = 0; nj < 4; nj++) {
            int m0r = bM + wm * 32 + mi * 16 + g;
            int n   = bN + wn * 32 + nj * 8 + t * 2;
            float b0 = bo[n], b1 = bo[n + 1];
            float2 v0 = make_float2(acc[mi][nj][0] + b0, acc[mi][nj][1] + b1);
            float2 v1 = make_float2(acc[mi][nj][2] + b0, acc[mi][nj][3] + b1);
            *(float2*)&outp[(size_t)m0r * EMB + n]       = v0;
            *(float2*)&outp[(size_t)(m0r + 8) * EMB + n] = v1;
        }
    }
}

// ---------------------------------------------------------------------------

extern "C" void kernel_launch(void* const* d_in, const int* in_sizes, int n_in,
                              void* d_out, int out_size)
{
    const float* x  = (const float*)d_in[0];
    const float* Wq = (const float*)d_in[1];
    const float* bq = (const float*)d_in[2];
    const float* Wk = (const float*)d_in[3];
    const float* bk = (const float*)d_in[4];
    const float* Wv = (const float*)d_in[5];
    const float* bv = (const float*)d_in[6];
    const float* Wo = (const float*)d_in[7];
    const float* bo = (const float*)d_in[8];
    float* out = (float*)d_out;

    const int attn_smem = 2 * WG_SMEM;                            // 58368 B
    const int outp_smem = (64 * ASTR + 32 * BSTR * 2) * 4;        // 44032 B
    cudaFuncSetAttribute(attn_kernel,
                         cudaFuncAttributeMaxDynamicSharedMemorySize, attn_smem);
    cudaFuncSetAttribute(out_proj_tf32,
                         cudaFuncAttributeMaxDynamicSharedMemorySize, outp_smem);

    proj_qkv_kernel<<<dim3(EMB / 128, SEQ / 128, 3), 256>>>(x, Wq, bq, Wk, bk, Wv, bv);
    attn_kernel<<<dim3(16, NH), 256, attn_smem>>>();
    out_proj_tf32<<<dim3(EMB / 128, SEQ / 64), 256, outp_smem>>>(Wo, bo, out);
}

// round 15
// speedup vs baseline: 1.3330x; 1.1204x over previous
#include <cuda_runtime.h>
#include <cuda_bf16.h>
#include <math.h>
#include <stdint.h>

#define SEQ 2048
#define EMB 1024
#define NH  16
#define HD  64

typedef unsigned long long u64;

// Scratch (device globals — no allocation allowed)
__device__ __nv_bfloat16 g_Q[NH * SEQ * HD];
__device__ __nv_bfloat16 g_K[NH * SEQ * HD];
__device__ __nv_bfloat16 g_V[NH * SEQ * HD];
// g_S: TILED layout [NH][32 qt][32 kt][64*64], scores then exp values
__device__ __nv_bfloat16 g_S[(size_t)NH * SEQ * SEQ];
__device__ float g_attn[SEQ * EMB];

__device__ __forceinline__ float bf16r(float v) {
    return __bfloat162float(__float2bfloat16(v));
}
__device__ __forceinline__ uint32_t f2tf32(float x) {
    uint32_t r;
    asm("cvt.rna.tf32.f32 %0, %1;" : "=r"(r) : "f"(x));
    return r;
}

// ---------------- packed f32x2 fma (Blackwell FFMA2) ----------------
// Each half is an independent fma.rn.f32 -> bitwise identical to scalar fmaf.
__device__ __forceinline__ void fma2(u64& d, u64 a, u64 b) {
    asm("fma.rn.f32x2 %0, %1, %2, %0;" : "+l"(d) : "l"(a), "l"(b));
}
__device__ __forceinline__ u64 bcast2(float v) {
    u64 r; asm("mov.b64 %0, {%1, %2};" : "=l"(r) : "f"(v), "f"(v)); return r;
}
__device__ __forceinline__ void unpack2(u64 p, float& lo, float& hi) {
    asm("mov.b64 {%0, %1}, %2;" : "=f"(lo), "=f"(hi) : "l"(p));
}

// ---------------- mma.sync helpers ----------------
__device__ __forceinline__ uint32_t smem_u32(const void* p) {
    return (uint32_t)__cvta_generic_to_shared(p);
}
__device__ __forceinline__ void ldsm_x4(uint32_t& a0, uint32_t& a1,
                                        uint32_t& a2, uint32_t& a3, uint32_t addr) {
    asm volatile("ldmatrix.sync.aligned.m8n8.x4.shared.b16 {%0,%1,%2,%3}, [%4];\n"
                 : "=r"(a0), "=r"(a1), "=r"(a2), "=r"(a3) : "r"(addr));
}
__device__ __forceinline__ void ldsm_x2(uint32_t& b0, uint32_t& b1, uint32_t addr) {
    asm volatile("ldmatrix.sync.aligned.m8n8.x2.shared.b16 {%0,%1}, [%2];\n"
                 : "=r"(b0), "=r"(b1) : "r"(addr));
}
__device__ __forceinline__ void ldsm_x2_t(uint32_t& b0, uint32_t& b1, uint32_t addr) {
    asm volatile("ldmatrix.sync.aligned.m8n8.x2.trans.shared.b16 {%0,%1}, [%2];\n"
                 : "=r"(b0), "=r"(b1) : "r"(addr));
}
__device__ __forceinline__ void mma16816(float& d0, float& d1, float& d2, float& d3,
                                         uint32_t a0, uint32_t a1, uint32_t a2, uint32_t a3,
                                         uint32_t b0, uint32_t b1) {
    asm volatile("mma.sync.aligned.m16n8k16.row.col.f32.bf16.bf16.f32 "
                 "{%0,%1,%2,%3},{%4,%5,%6,%7},{%8,%9},{%0,%1,%2,%3};\n"
                 : "+f"(d0), "+f"(d1), "+f"(d2), "+f"(d3)
                 : "r"(a0), "r"(a1), "r"(a2), "r"(a3), "r"(b0), "r"(b1));
}
__device__ __forceinline__ void mma_tf32(float* d, const uint32_t* a,
                                         const uint32_t* b) {
    asm volatile("mma.sync.aligned.m16n8k8.row.col.f32.tf32.tf32.f32 "
                 "{%0,%1,%2,%3},{%4,%5,%6,%7},{%8,%9},{%0,%1,%2,%3};\n"
                 : "+f"(d[0]), "+f"(d[1]), "+f"(d[2]), "+f"(d[3])
                 : "r"(a[0]), "r"(a[1]), "r"(a[2]), "r"(a[3]), "r"(b[0]), "r"(b[1]));
}

// ---------------- cp.async helpers ----------------
__device__ __forceinline__ void cp_async16(uint32_t smem_addr, const void* gptr) {
    asm volatile("cp.async.cg.shared.global [%0], [%1], 16;\n"
                 :: "r"(smem_addr), "l"(gptr));
}
__device__ __forceinline__ void cp_commit() {
    asm volatile("cp.async.commit_group;\n" ::: "memory");
}
__device__ __forceinline__ void cp_wait0() {
    asm volatile("cp.async.wait_group 0;\n" ::: "memory");
}
__device__ __forceinline__ void bar_sync(int id) {
    asm volatile("bar.sync %0, 128;\n" :: "r"(id) : "memory");
}

// ---------------------------------------------------------------------------
// Fused QKV projection — sequential-K FFMA2 chains (bit-exact), Kc=8,
// double-buffered smem, register prefetch. NEW: each thread's 8 output
// columns are split as {tx*4..+3, tx*4+64..+67} so B-fragment LDS.128 reads
// are bank-conflict-free (was 4-way conflicted at tx*8).
// Per-output FMA order unchanged -> bitwise identical results.
// ---------------------------------------------------------------------------
__global__ __launch_bounds__(256) void proj_qkv_kernel(
    const float* __restrict__ x,
    const float* __restrict__ Wq, const float* __restrict__ bq,
    const float* __restrict__ Wk, const float* __restrict__ bk,
    const float* __restrict__ Wv, const float* __restrict__ bv)
{
    const float* W; const float* bias; __nv_bfloat16* out;
    if (blockIdx.z == 0)      { W = Wq; bias = bq; out = g_Q; }
    else if (blockIdx.z == 1) { W = Wk; bias = bk; out = g_K; }
    else                      { W = Wv; bias = bv; out = g_V; }

    __shared__ float As[2][8][128];
    __shared__ float Bs[2][8][128];
    const int tid = threadIdx.x;
    const int tx = tid & 15, ty = tid >> 4;
    const int bM = blockIdx.y * 128, bN = blockIdx.x * 128;

    const int ar = tid >> 1, ac = (tid & 1) * 4;
    const int br = tid >> 5, bc = (tid & 31) * 4;

    // acc2[i][jp]: jp 0-1 -> cols tx*4 + {0,1},{2,3}; jp 2-3 -> +64
    u64 acc2[8][4] = {};

    float4 pa = *(const float4*)(x + (size_t)(bM + ar) * EMB + ac);
    float4 pb = *(const float4*)(W + (size_t)br * EMB + bN + bc);

    for (int k0 = 0; k0 < EMB; k0 += 8) {
        const int b = (k0 >> 3) & 1;
        As[b][ac + 0][ar] = pa.x; As[b][ac + 1][ar] = pa.y;
        As[b][ac + 2][ar] = pa.z; As[b][ac + 3][ar] = pa.w;
        *(float4*)&Bs[b][br][bc] = pb;
        __syncthreads();

        if (k0 + 8 < EMB) {
            pa = *(const float4*)(x + (size_t)(bM + ar) * EMB + k0 + 8 + ac);
            pb = *(const float4*)(W + (size_t)(k0 + 8 + br) * EMB + bN + bc);
        }

        #pragma unroll
        for (int kk = 0; kk < 8; kk++) {
            float a[8];
            *(float4*)&a[0]  = *(float4*)&As[b][kk][ty * 8];
            *(float4*)&a[4]  = *(float4*)&As[b][kk][ty * 8 + 4];
            // two conflict-free LDS.128: banks tx*4 cover 0..31 across lanes
            float4 b4a = *(float4*)&Bs[b][kk][tx * 4];
            float4 b4b = *(float4*)&Bs[b][kk][tx * 4 + 64];
            u64 bb2[4];
            bb2[0] = ((u64*)&b4a)[0];
            bb2[1] = ((u64*)&b4a)[1];
            bb2[2] = ((u64*)&b4b)[0];
            bb2[3] = ((u64*)&b4b)[1];
            #pragma unroll
            for (int i = 0; i < 8; i++) {
                u64 ai = bcast2(a[i]);
                #pragma unroll
                for (int jp = 0; jp < 4; jp++)
                    fma2(acc2[i][jp], ai, bb2[jp]);
            }
        }
    }

    #pragma unroll
    for (int i = 0; i < 8; i++) {
        int m = bM + ty * 8 + i;
        #pragma unroll
        for (int jp = 0; jp < 4; jp++) {
            float v0, v1;
            unpack2(acc2[i][jp], v0, v1);
            int n = bN + tx * 4 + (jp >> 1) * 64 + (jp & 1) * 2;
            float r0 = v0 + bias[n];
            float r1 = v1 + bias[n + 1];
            out[(size_t)(n >> 6) * SEQ * HD + (size_t)m * HD + (n & 63)] =
                __float2bfloat16(r0);
            out[(size_t)((n + 1) >> 6) * SEQ * HD + (size_t)m * HD + ((n + 1) & 63)] =
                __float2bfloat16(r1);
        }
    }
}

// ---------------------------------------------------------------------------
// Causal attention — byte-identical to round 13/14 (bit-safe, tiled g_S).
// ---------------------------------------------------------------------------
__device__ __forceinline__ void stage_tile(uint32_t dst, const __nv_bfloat16* src,
                                           int wtid) {
    #pragma unroll
    for (int u = 0; u < 4; u++) {
        int idx = wtid + u * 128;
        int r = idx >> 3, s = idx & 7;
        cp_async16(dst + (uint32_t)((r * 72 + s * 8) * 2), src + r * 64 + s * 8);
    }
}

__device__ void attn_qtile(
    int qt, int h, __nv_bfloat16* Qs, __nv_bfloat16* KV2,
    float* mrow, float* Lrow, float* psum, int wtid, int barid)
{
    const int lane = wtid & 31;
    const int warp = wtid >> 5;
    const int r0   = warp * 16;

    const size_t qbase = ((size_t)h * SEQ + (size_t)qt * 64) * HD;
    const size_t tile0 = (((size_t)h * 32 + qt) * 32) * 4096;  // kt-tile base
    const __nv_bfloat16* Kh = g_K + (size_t)h * SEQ * HD;
    const __nv_bfloat16* Vh = g_V + (size_t)h * SEQ * HD;

    const uint32_t kvb0 = smem_u32(KV2);
    const uint32_t kvb1 = kvb0 + 64 * 72 * 2;

    for (int idx = wtid; idx < 64 * 8; idx += 128) {
        int r = idx >> 3, s = idx & 7;
        *(uint4*)&Qs[r * 72 + s * 8] = *(const uint4*)&g_Q[qbase + r * 64 + s * 8];
    }
    bar_sync(barid);

    uint32_t aq[4][4];
    {
        const uint32_t qb = smem_u32(Qs);
        #pragma unroll
        for (int ks = 0; ks < 4; ks++) {
            uint32_t addr = qb +
                (uint32_t)((r0 + (lane & 7) + ((lane >> 3) & 1) * 8) * 144 +
                           ((lane >> 4) * 16) + ks * 32);
            ldsm_x4(aq[ks][0], aq[ks][1], aq[ks][2], aq[ks][3], addr);
        }
    }

    // ================= PHASE 1: S -> g_S tiles, running row max ============
    float rm0 = -INFINITY, rm1 = -INFINITY;
    const int rA = r0 + (lane >> 2);

    stage_tile(kvb0, Kh, wtid);
    cp_commit();

    for (int kt = 0; kt <= qt; kt++) {
        cp_wait0();
        bar_sync(barid);
        const uint32_t kvb = (kt & 1) ? kvb1 : kvb0;
        if (kt < qt) {
            stage_tile((kt & 1) ? kvb0 : kvb1, Kh + (size_t)(kt + 1) * 64 * HD, wtid);
            cp_commit();
        }

        const size_t tb = tile0 + (size_t)kt * 4096;
        const bool diag = (kt == qt);
        #pragma unroll
        for (int nt = 0; nt < 8; nt++) {
            float c0 = 0.f, c1 = 0.f, c2 = 0.f, c3 = 0.f;
            #pragma unroll
            for (int ks = 0; ks < 4; ks++) {
                int l2 = lane & 15;
                uint32_t addr = kvb +
                    (uint32_t)((nt * 8 + (l2 & 7)) * 144 + (l2 >> 3) * 16 + ks * 32);
                uint32_t b0, b1;
                ldsm_x2(b0, b1, addr);
                mma16816(c0, c1, c2, c3,
                         aq[ks][0], aq[ks][1], aq[ks][2], aq[ks][3], b0, b1);
            }
            const int cc = nt * 8 + (lane & 3) * 2;
            float s00 = bf16r(c0) * 0.5f;
            float s01 = bf16r(c1) * 0.5f;
            float s10 = bf16r(c2) * 0.5f;
            float s11 = bf16r(c3) * 0.5f;
            if (diag) {
                if (cc     > rA)     s00 = -INFINITY;
                if (cc + 1 > rA)     s01 = -INFINITY;
                if (cc     > rA + 8) s10 = -INFINITY;
                if (cc + 1 > rA + 8) s11 = -INFINITY;
            }
            rm0 = fmaxf(rm0, fmaxf(s00, s01));
            rm1 = fmaxf(rm1, fmaxf(s10, s11));
            __nv_bfloat162 p0; p0.x = __float2bfloat16(s00); p0.y = __float2bfloat16(s01);
            __nv_bfloat162 p1; p1.x = __float2bfloat16(s10); p1.y = __float2bfloat16(s11);
            *(uint32_t*)&g_S[tb + (size_t)rA * 64 + cc]       = *(uint32_t*)&p0;
            *(uint32_t*)&g_S[tb + (size_t)(rA + 8) * 64 + cc] = *(uint32_t*)&p1;
        }
    }
    rm0 = fmaxf(rm0, __shfl_xor_sync(0xFFFFFFFFu, rm0, 1));
    rm0 = fmaxf(rm0, __shfl_xor_sync(0xFFFFFFFFu, rm0, 2));
    rm1 = fmaxf(rm1, __shfl_xor_sync(0xFFFFFFFFu, rm1, 1));
    rm1 = fmaxf(rm1, __shfl_xor_sync(0xFFFFFFFFu, rm1, 2));
    if ((lane & 3) == 0) {
        mrow[rA]     = rm0;
        mrow[rA + 8] = rm1;
    }
    bar_sync(barid);

    // ====== PHASE 2: e -> g_S (same value/order chain) =====================
    for (int rb = 0; rb < 64; rb += 32) {
        const int r = rb + (wtid >> 2), seg = wtid & 3;
        const float m = mrow[r];
        float part = 0.f;
        for (int ktt = 0; ktt <= qt; ktt++) {
            __nv_bfloat16* tp = &g_S[tile0 + (size_t)ktt * 4096 + (size_t)r * 64];
            #pragma unroll 4
            for (int c = seg; c < 64; c += 4) {
                float s = __bfloat162float(tp[c]);
                float t = bf16r(s - m);
                float e = bf16r(expf(t));
                part += e;
                tp[c] = __float2bfloat16(e);
            }
        }
        psum[r * 4 + seg] = part;
    }
    bar_sync(barid);
    if (wtid < 64) {
        float L32 = ((psum[wtid * 4 + 0] + psum[wtid * 4 + 1]) +
                      psum[wtid * 4 + 2]) + psum[wtid * 4 + 3];
        Lrow[wtid] = bf16r(L32);
    }
    bar_sync(barid);

    // ================= PHASE 3: p = bf16(e * (1/L)), O = P @ V =============
    const float rL0 = 1.0f / Lrow[rA];
    const float rL1 = 1.0f / Lrow[rA + 8];

    float o[8][4];
    #pragma unroll
    for (int nt = 0; nt < 8; nt++)
        #pragma unroll
        for (int i = 0; i < 4; i++) o[nt][i] = 0.f;

    stage_tile(kvb0, Vh, wtid);
    cp_commit();

    for (int kt = 0; kt <= qt; kt++) {
        cp_wait0();
        bar_sync(barid);
        const uint32_t kvb = (kt & 1) ? kvb1 : kvb0;
        if (kt < qt) {
            stage_tile((kt & 1) ? kvb0 : kvb1, Vh + (size_t)(kt + 1) * 64 * HD, wtid);
            cp_commit();
        }

        const size_t tb  = tile0 + (size_t)kt * 4096;
        const size_t rowA = tb + (size_t)rA * 64;
        const size_t rowB = tb + (size_t)(rA + 8) * 64;

        uint32_t pa[4][4];
        #pragma unroll
        for (int ks = 0; ks < 4; ks++) {
            const int col = ks * 16 + (lane & 3) * 2;   // within-tile column
            #pragma unroll
            for (int half = 0; half < 2; half++) {
                uint32_t sA = *(const uint32_t*)&g_S[rowA + col + half * 8];
                uint32_t sB = *(const uint32_t*)&g_S[rowB + col + half * 8];
                __nv_bfloat162 eA = *(__nv_bfloat162*)&sA;
                __nv_bfloat162 eB = *(__nv_bfloat162*)&sB;
                __nv_bfloat162 fA, fB;
                fA.x = __float2bfloat16(__bfloat162float(eA.x) * rL0);
                fA.y = __float2bfloat16(__bfloat162float(eA.y) * rL0);
                fB.x = __float2bfloat16(__bfloat162float(eB.x) * rL1);
                fB.y = __float2bfloat16(__bfloat162float(eB.y) * rL1);
                pa[ks][half * 2 + 0] = *(uint32_t*)&fA;
                pa[ks][half * 2 + 1] = *(uint32_t*)&fB;
            }
        }

        #pragma unroll
        for (int nt = 0; nt < 8; nt++) {
            #pragma unroll
            for (int ks = 0; ks < 4; ks++) {
                int l2 = lane & 15;
                uint32_t addr = kvb + (uint32_t)((ks * 16 + l2) * 144 + nt * 16);
                uint32_t b0, b1;
                ldsm_x2_t(b0, b1, addr);
                mma16816(o[nt][0], o[nt][1], o[nt][2], o[nt][3],
                         pa[ks][0], pa[ks][1], pa[ks][2], pa[ks][3], b0, b1);
            }
        }
    }

    const int qg0 = qt * 64;
    #pragma unroll
    for (int nt = 0; nt < 8; nt++) {
        const int colb = h * 64 + nt * 8 + (lane & 3) * 2;
        float2 vA = make_float2(bf16r(o[nt][0]), bf16r(o[nt][1]));
        float2 vB = make_float2(bf16r(o[nt][2]), bf16r(o[nt][3]));
        *(float2*)&g_attn[(size_t)(qg0 + rA) * EMB + colb]     = vA;
        *(float2*)&g_attn[(size_t)(qg0 + rA + 8) * EMB + colb] = vB;
    }
}

// per-WG smem partition: Qs 9216 B, KV2 18432 B, mrow 256, Lrow 256, psum 1024
#define WG_SMEM (9216 + 18432 + 256 + 256 + 1024)   // 29184 B

__global__ __launch_bounds__(256) void attn_kernel()
{
    extern __shared__ char asm_smem[];
    const int wg   = threadIdx.x >> 7;     // 0 or 1
    const int wtid = threadIdx.x & 127;

    char* base = asm_smem + wg * WG_SMEM;
    __nv_bfloat16* Qs  = (__nv_bfloat16*)base;
    __nv_bfloat16* KV2 = (__nv_bfloat16*)(base + 9216);
    float* mrow = (float*)(base + 9216 + 18432);
    float* Lrow = mrow + 64;
    float* psum = Lrow + 64;

    const int h  = blockIdx.y;
    const int qt = wg ? (31 - (int)blockIdx.x) : (int)blockIdx.x;
    attn_qtile(qt, h, Qs, KV2, mrow, Lrow, psum, wtid, wg + 1);
}

// ---------------------------------------------------------------------------
// Output projection, 2xTF32, 64m x 128n tiles + register prefetch — EXACT
// round-13/14 version (validated).
// ---------------------------------------------------------------------------
#define ASTR 36
#define BSTR 136

__global__ __launch_bounds__(256) void out_proj_tf32(
    const float* __restrict__ Wo, const float* __restrict__ bo,
    float* __restrict__ outp)
{
    extern __shared__ uint32_t dsm[];
    uint32_t* Ah = dsm;                    // [64][ASTR]
    uint32_t* Bh = Ah + 64 * ASTR;         // [32][BSTR]
    uint32_t* Bl = Bh + 32 * BSTR;

    const int tid = threadIdx.x, lane = tid & 31, warp = tid >> 5;
    const int wm = warp >> 2, wn = warp & 3;
    const int g = lane >> 2, t = lane & 3;
    const int bM = blockIdx.y * 64, bN = blockIdx.x * 128;

    const int a_row = tid >> 3, a_c = (tid & 7) * 4;
    const int a_row1 = (tid + 256) >> 3, a_c1 = ((tid + 256) & 7) * 4;
    float acc[2][4][4] = {};

    float4 pa0 = *(const float4*)(g_attn + (size_t)(bM + a_row) * EMB + a_c);
    float4 pa1 = *(const float4*)(g_attn + (size_t)(bM + a_row1) * EMB + a_c1);
    float4 pb[4];
    #pragma unroll
    for (int u = 0; u < 4; u++) {
        int idx = tid + u * 256;
        pb[u] = *(const float4*)(Wo + (size_t)(idx >> 5) * EMB + bN + (idx & 31) * 4);
    }

    for (int k0 = 0; k0 < EMB; k0 += 32) {
        {
            uint4 h;
            h.x = f2tf32(pa0.x); h.y = f2tf32(pa0.y);
            h.z = f2tf32(pa0.z); h.w = f2tf32(pa0.w);
            *(uint4*)&Ah[a_row * ASTR + a_c] = h;
            h.x = f2tf32(pa1.x); h.y = f2tf32(pa1.y);
            h.z = f2tf32(pa1.z); h.w = f2tf32(pa1.w);
            *(uint4*)&Ah[a_row1 * ASTR + a_c1] = h;
        }
        #pragma unroll
        for (int u = 0; u < 4; u++) {
            int idx = tid + u * 256;
            int kr = idx >> 5, c4 = (idx & 31) * 4;
            float4 v = pb[u];
            uint4 h, l;
            h.x = f2tf32(v.x); l.x = f2tf32(v.x - __uint_as_float(h.x));
            h.y = f2tf32(v.y); l.y = f2tf32(v.y - __uint_as_float(h.y));
            h.z = f2tf32(v.z); l.z = f2tf32(v.z - __uint_as_float(h.z));
            h.w = f2tf32(v.w); l.w = f2tf32(v.w - __uint_as_float(h.w));
            *(uint4*)&Bh[kr * BSTR + c4] = h;
            *(uint4*)&Bl[kr * BSTR + c4] = l;
        }
        __syncthreads();

        if (k0 + 32 < EMB) {
            pa0 = *(const float4*)(g_attn + (size_t)(bM + a_row) * EMB + k0 + 32 + a_c);
            pa1 = *(const float4*)(g_attn + (size_t)(bM + a_row1) * EMB + k0 + 32 + a_c1);
            #pragma unroll
            for (int u = 0; u < 4; u++) {
                int idx = tid + u * 256;
                pb[u] = *(const float4*)(Wo + (size_t)(k0 + 32 + (idx >> 5)) * EMB +
                                         bN + (idx & 31) * 4);
            }
        }

        #pragma unroll
        for (int ks = 0; ks < 4; ks++) {
            uint32_t ah[2][4], bh[4][2], bl[4][2];
            #pragma unroll
            for (int mi = 0; mi < 2; mi++) {
                int base = (wm * 32 + mi * 16 + g) * ASTR + ks * 8 + t;
                ah[mi][0] = Ah[base];
                ah[mi][1] = Ah[base + 8 * ASTR];
                ah[mi][2] = Ah[base + 4];
                ah[mi][3] = Ah[base + 8 * ASTR + 4];
            }
            #pragma unroll
            for (int nj = 0; nj < 4; nj++) {
                int base = (ks * 8 + t) * BSTR + wn * 32 + nj * 8 + g;
                bh[nj][0] = Bh[base];
                bh[nj][1] = Bh[base + 4 * BSTR];
                bl[nj][0] = Bl[base];
                bl[nj][1] = Bl[base + 4 * BSTR];
            }
            #pragma unroll
            for (int mi = 0; mi < 2; mi++)
                #pragma unroll
                for (int nj = 0; nj < 4; nj++) {
                    mma_tf32(acc[mi][nj], ah[mi], bh[nj]);
                    mma_tf32(acc[mi][nj], ah[mi], bl[nj]);
                }
        }
        __syncthreads();
    }

    #pragma unroll
    for (int mi = 0; mi < 2; mi++) {
        #pragma unroll
        for (int nj = 0; nj < 4; nj++) {
            int m0r = bM + wm * 32 + mi * 16 + g;
            int n   = bN + wn * 32 + nj * 8 + t * 2;
            float b0 = bo[n], b1 = bo[n + 1];
            float2 v0 = make_float2(acc[mi][nj][0] + b0, acc[mi][nj][1] + b1);
            float2 v1 = make_float2(acc[mi][nj][2] + b0, acc[mi][nj][3] + b1);
            *(float2*)&outp[(size_t)m0r * EMB + n]       = v0;
            *(float2*)&outp[(size_t)(m0r + 8) * EMB + n] = v1;
        }
    }
}

// ---------------------------------------------------------------------------

extern "C" void kernel_launch(void* const* d_in, const int* in_sizes, int n_in,
                              void* d_out, int out_size)
{
    const float* x  = (const float*)d_in[0];
    const float* Wq = (const float*)d_in[1];
    const float* bq = (const float*)d_in[2];
    const float* Wk = (const float*)d_in[3];
    const float* bk = (const float*)d_in[4];
    const float* Wv = (const float*)d_in[5];
    const float* bv = (const float*)d_in[6];
    const float* Wo = (const float*)d_in[7];
    const float* bo = (const float*)d_in[8];
    float* out = (float*)d_out;

    const int attn_smem = 2 * WG_SMEM;                            // 58368 B
    const int outp_smem = (64 * ASTR + 32 * BSTR * 2) * 4;        // 44032 B
    cudaFuncSetAttribute(attn_kernel,
                         cudaFuncAttributeMaxDynamicSharedMemorySize, attn_smem);
    cudaFuncSetAttribute(out_proj_tf32,
                         cudaFuncAttributeMaxDynamicSharedMemorySize, outp_smem);

    proj_qkv_kernel<<<dim3(EMB / 128, SEQ / 128, 3), 256>>>(x, Wq, bq, Wk, bk, Wv, bv);
    attn_kernel<<<dim3(16, NH), 256, attn_smem>>>();
    out_proj_tf32<<<dim3(EMB / 128, SEQ / 64), 256, outp_smem>>>(Wo, bo, out);
}